// round 11
// baseline (speedup 1.0000x reference)
#include <cuda_runtime.h>
#include <cuda_fp16.h>
#include <cstdint>

#define N_NODES 8192
#define D_FEAT  128
#define C_CLS   10
#define T_TRAIN 1024
#define ND (N_NODES * D_FEAT)

#define INV_SCALE (1.0f / 4096.0f)

// ---------------- scratch (device globals; no allocation allowed) ----------------
__device__ __align__(128) __half g_Sh[N_NODES * 256];    // [s_r|s_i] node-major fp16
__device__ __align__(128) __half g_STh[256 * N_NODES];   // S^T fp16 [256,8192] K-major (GEMM B)
__device__ __align__(128) float  g_Msg[N_NODES * 256];   // combined msg [8192,256] (atomic accum)
__device__ __align__(128) float  g_in[2 * N_NODES];      // in_r, in_i
__device__ __align__(128) float  g_pn[N_NODES * C_CLS];  // pseudo_norm
__device__ __align__(128) float  g_Wbig[256 * 256];      // [[Wr,-Wi],[Wi,Wr]] K-major

// ---------------- helpers ----------------
__device__ __forceinline__ void cp16(uint32_t smem, const void* g) {
    asm volatile("cp.async.cg.shared.global [%0], [%1], 16;\n" :: "r"(smem), "l"(g));
}
// exact x4096 via exponent add (adj >= 0; 0 stays ~0 after f16 round)
__device__ __forceinline__ uint32_t packh2_scaled(float x, float y) {
    float xs = __uint_as_float(__float_as_uint(x) + 0x06000000u);
    float ys = __uint_as_float(__float_as_uint(y) + 0x06000000u);
    __half2 h = __floats2half2_rn(xs, ys);
    return *reinterpret_cast<uint32_t*>(&h);
}
#define LDSM_X4(r0, r1, r2, r3, addr) \
    asm volatile("ldmatrix.sync.aligned.m8n8.x4.shared.b16 {%0,%1,%2,%3}, [%4];" \
        : "=r"(r0), "=r"(r1), "=r"(r2), "=r"(r3) : "r"(addr))

// ---------------- K_zero: clear g_Msg ----------------
__global__ void k_zero() {
    int i = blockIdx.x * 512 + threadIdx.x;   // 2M float4
    reinterpret_cast<float4*>(g_Msg)[i] = make_float4(0.f, 0.f, 0.f, 0.f);
}

// ---------------- K0: build combined MLP weight ----------------
__global__ void k_build_wbig(const float* __restrict__ Wr, const float* __restrict__ Wi) {
    int idx = blockIdx.x * 256 + threadIdx.x;
    int d = idx >> 8, e = idx & 255;
    float v;
    if (d < 128) v = (e < 128) ? Wr[d * 128 + e] : -Wi[d * 128 + (e - 128)];
    else {
        int dd = d - 128;
        v = (e < 128) ? Wi[dd * 128 + e] : Wr[dd * 128 + (e - 128)];
    }
    g_Wbig[idx] = v;
}

// ---------------- K1: per-node prep ----------------
__global__ __launch_bounds__(256) void k_node_prep(
    const float* __restrict__ xr_g, const float* __restrict__ xi_g,
    const float* __restrict__ Wcr, const float* __restrict__ Wci,
    const float* __restrict__ bcr, const float* __restrict__ bci,
    const float* __restrict__ thr, const float* __restrict__ thi)
{
    __shared__ float sWr[C_CLS * 128], sWi[C_CLS * 128];
    __shared__ float sb[4 * C_CLS];
    int tid = threadIdx.x;
    for (int i = tid; i < C_CLS * 128; i += 256) { sWr[i] = Wcr[i]; sWi[i] = Wci[i]; }
    if (tid < C_CLS) {
        sb[tid] = bcr[tid]; sb[C_CLS + tid] = bci[tid];
        sb[2 * C_CLS + tid] = thr[tid]; sb[3 * C_CLS + tid] = thi[tid];
    }
    __syncthreads();

    int wid = tid >> 5, lane = tid & 31;
    int j = blockIdx.x * 8 + wid;

    float xr[4], xi[4];
#pragma unroll
    for (int k = 0; k < 4; k++) {
        xr[k] = xr_g[j * 128 + lane + 32 * k];
        xi[k] = xi_g[j * 128 + lane + 32 * k];
    }

    float pn[C_CLS];
#pragma unroll
    for (int c = 0; c < C_CLS; c++) {
        float p1 = 0.f, p2 = 0.f, p3 = 0.f, p4 = 0.f;
#pragma unroll
        for (int k = 0; k < 4; k++) {
            float wr = sWr[c * 128 + lane + 32 * k];
            float wi = sWi[c * 128 + lane + 32 * k];
            p1 += xr[k] * wr; p2 += xi[k] * wr;
            p3 += xi[k] * wi; p4 += xr[k] * wi;
        }
#pragma unroll
        for (int off = 16; off; off >>= 1) {
            p1 += __shfl_xor_sync(0xffffffffu, p1, off);
            p2 += __shfl_xor_sync(0xffffffffu, p2, off);
            p3 += __shfl_xor_sync(0xffffffffu, p3, off);
            p4 += __shfl_xor_sync(0xffffffffu, p4, off);
        }
        float cr = p1 + sb[c] - p3 - sb[C_CLS + c];
        float ci = p2 + sb[c] + p4 + sb[C_CLS + c];
        pn[c] = sqrtf(cr * cr + ci * ci);
    }

    float m = pn[0];
#pragma unroll
    for (int c = 1; c < C_CLS; c++) m = fmaxf(m, pn[c]);
    float s = 0.f, e[C_CLS];
#pragma unroll
    for (int c = 0; c < C_CLS; c++) { e[c] = expf(pn[c] - m); s += e[c]; }
    float inv = 1.0f / s, inr = 0.f, ini = 0.f;
#pragma unroll
    for (int c = 0; c < C_CLS; c++) {
        float sc = e[c] * inv;
        inr += sc * sb[2 * C_CLS + c];
        ini += sc * sb[3 * C_CLS + c];
    }

    if (lane == 0) {
#pragma unroll
        for (int c = 0; c < C_CLS; c++) g_pn[j * C_CLS + c] = pn[c];
        g_in[j] = inr; g_in[N_NODES + j] = ini;
    }

#pragma unroll
    for (int k = 0; k < 4; k++) {
        int d = lane + 32 * k;
        g_Sh[j * 256 + d]       = __float2half(inr * xr[k] + ini * xi[k]);
        g_Sh[j * 256 + 128 + d] = __float2half(inr * xi[k] - ini * xr[k]);
    }
}

// ---------------- K1b: transpose g_Sh [8192,256] -> g_STh [256,8192] ----------------
__global__ void k_transp() {
    __shared__ __half t[32][33];
    int bx = blockIdx.x;
    int by = blockIdx.y;
    int lx = threadIdx.x, ly = threadIdx.y;
#pragma unroll
    for (int i = 0; i < 32; i += 8)
        t[ly + i][lx] = g_Sh[(size_t)(bx * 32 + ly + i) * 256 + by * 32 + lx];
    __syncthreads();
#pragma unroll
    for (int i = 0; i < 32; i += 8)
        g_STh[(size_t)(by * 32 + ly + i) * N_NODES + bx * 32 + lx] = t[lx][ly + i];
}

// ================= GEMM1: fp16 mma.sync + ldmatrix, BK=64, fused atomic epilogue =================
// 128x256 CTA tile, 8 warps; warp tile 64(m) x (32 real + 32 imag paired cols).
#define BM 128
#define BN 256
#define BK 64
#define NSPLIT 2
#define KSPLIT (N_NODES / NSPLIT)    // 4096
#define NKT (KSPLIT / BK)            // 64
#define ASTR 72                      // halfs per A smem row (144B, 16B-mult, LDSM conflict-free)
#define BSTR 72                      // halfs per B smem row
#define ASTAGE (BM * ASTR)           // halfs/stage (2 stages)
#define BSTAGE (BN * BSTR)           // halfs/stage (3 stages)
#define SMEM_G1 ((2 * ASTAGE + 3 * BSTAGE) * 2)   // 147456 B

__global__ __launch_bounds__(256, 1) void k_gemm1(const float* __restrict__ adj) {
    extern __shared__ __align__(16) char smraw[];
    __half* Ah = reinterpret_cast<__half*>(smraw);
    __half* Bs = reinterpret_cast<__half*>(smraw + 2 * ASTAGE * 2);

    int tid = threadIdx.x;
    int m0 = blockIdx.x * BM;
    int kb = blockIdx.z * KSPLIT;
    const float*  Ag = adj + (size_t)m0 * N_NODES + kb;
    const __half* Bg = g_STh + kb;

    uint32_t sAh = (uint32_t)__cvta_generic_to_shared(Ah);
    uint32_t sB  = (uint32_t)__cvta_generic_to_shared(Bs);

    // A: thread t -> row t>>1, 32 cols at (t&1)*32; packed to f16 at LDG time
    int ar = tid >> 1, ac = (tid & 1) * 32;
    uint32_t pd[16];
    auto ldgA = [&](int kt) {
        const float4* p = reinterpret_cast<const float4*>(
            Ag + (size_t)ar * N_NODES + kt * BK + ac);
#pragma unroll
        for (int i = 0; i < 8; i++) {
            float4 v = p[i];
            pd[2 * i]     = packh2_scaled(v.x, v.y);
            pd[2 * i + 1] = packh2_scaled(v.z, v.w);
        }
    };
    auto stsA = [&](int st) {
        uint4* dst = reinterpret_cast<uint4*>(Ah + st * ASTAGE + ar * ASTR + ac);
#pragma unroll
        for (int i = 0; i < 4; i++)
            dst[i] = make_uint4(pd[4 * i], pd[4 * i + 1], pd[4 * i + 2], pd[4 * i + 3]);
    };

    auto loadB = [&](int kt) {
        int st = kt % 3;
        int k0 = kt * BK;
#pragma unroll
        for (int i = 0; i < 8; i++) {               // 2048 vec16 / 256 thr
            int v = tid + i * 256;
            int r = v >> 3, c = v & 7;
            cp16(sB + (uint32_t)(st * BSTAGE + r * BSTR + c * 8) * 2,
                 Bg + (size_t)r * N_NODES + k0 + c * 8);
        }
        asm volatile("cp.async.commit_group;\n");
    };

    float acc[4][8][4];
#pragma unroll
    for (int a = 0; a < 4; a++)
#pragma unroll
        for (int b = 0; b < 8; b++)
#pragma unroll
            for (int c = 0; c < 4; c++) acc[a][b][c] = 0.f;

    int wid = tid >> 5, lane = tid & 31;
    int wm = (wid & 1) * 64;        // 2 m-groups
    int wn2 = (wid >> 1) * 32;      // 4 n-groups; cols [wn2,wn2+32) real + [128+wn2,...) imag

    uint32_t Af[2][16], Bf[2][16];
    int a_row = lane & 15, a_half = (lane >> 4) * 8;
    int b_q = lane >> 3, b_r = lane & 7;
    int b_nfo = (b_q >> 1), b_half = (b_q & 1) * 8;

    auto fragload = [&](int buf, int ast, int bst, int k0) {
#pragma unroll
        for (int mf = 0; mf < 4; mf++) {
            uint32_t ad = sAh + (uint32_t)(ast * ASTAGE +
                (wm + mf * 16 + a_row) * ASTR + k0 + a_half) * 2;
            LDSM_X4(Af[buf][mf * 4 + 0], Af[buf][mf * 4 + 1],
                    Af[buf][mf * 4 + 2], Af[buf][mf * 4 + 3], ad);
        }
#pragma unroll
        for (int p = 0; p < 4; p++) {
            int nfb = p * 2 + b_nfo;
            int row = (nfb < 4) ? (wn2 + nfb * 8 + b_r)
                                : (128 + wn2 + (nfb - 4) * 8 + b_r);
            uint32_t ad = sB + (uint32_t)(bst * BSTAGE + row * BSTR + k0 + b_half) * 2;
            LDSM_X4(Bf[buf][p * 4 + 0], Bf[buf][p * 4 + 1],
                    Bf[buf][p * 4 + 2], Bf[buf][p * 4 + 3], ad);
        }
    };

    auto mma_all = [&](int buf) {
#pragma unroll
        for (int nf = 0; nf < 8; nf++) {
            uint32_t b0 = Bf[buf][(nf >> 1) * 4 + (nf & 1) * 2];
            uint32_t b1 = Bf[buf][(nf >> 1) * 4 + (nf & 1) * 2 + 1];
#pragma unroll
            for (int mf = 0; mf < 4; mf++) {
                asm volatile(
                    "mma.sync.aligned.m16n8k16.row.col.f32.f16.f16.f32 "
                    "{%0,%1,%2,%3}, {%4,%5,%6,%7}, {%8,%9}, {%0,%1,%2,%3};\n"
                    : "+f"(acc[mf][nf][0]), "+f"(acc[mf][nf][1]),
                      "+f"(acc[mf][nf][2]), "+f"(acc[mf][nf][3])
                    : "r"(Af[buf][mf * 4 + 0]), "r"(Af[buf][mf * 4 + 1]),
                      "r"(Af[buf][mf * 4 + 2]), "r"(Af[buf][mf * 4 + 3]),
                      "r"(b0), "r"(b1));
            }
        }
    };

    // prologue
    ldgA(0);
    loadB(0); loadB(1);
    stsA(0);
    ldgA(1);
    asm volatile("cp.async.wait_group 1;\n");
    __syncthreads();

    for (int kt = 0; kt < NKT; kt++) {
        int ast = kt & 1, bst = kt % 3;
        fragload(0, ast, bst, 0);
        fragload(1, ast, bst, 16);
        mma_all(0);
        if (kt + 1 < NKT) stsA((kt + 1) & 1);
        fragload(0, ast, bst, 32);
        mma_all(1);
        if (kt + 2 < NKT) ldgA(kt + 2);
        fragload(1, ast, bst, 48);
        mma_all(0);
        if (kt + 2 < NKT) loadB(kt + 2);
        mma_all(1);
        if (kt + 1 < NKT) {
            if (kt + 2 < NKT) asm volatile("cp.async.wait_group 1;\n");
            else              asm volatile("cp.async.wait_group 0;\n");
            __syncthreads();
        }
    }

    // fused epilogue: msg += diag(in) * acc * INV_SCALE   (complex combine, atomic)
    int g = lane >> 2, tg = lane & 3;
#pragma unroll
    for (int mf = 0; mf < 4; mf++) {
        int r0 = m0 + wm + mf * 16 + g;
        float inr0 = g_in[r0],     ini0 = g_in[N_NODES + r0];
        float inr8 = g_in[r0 + 8], ini8 = g_in[N_NODES + r0 + 8];
#pragma unroll
        for (int nfr = 0; nfr < 4; nfr++) {
            int c = wn2 + nfr * 8 + 2 * tg;
#pragma unroll
            for (int q = 0; q < 4; q++) {
                int row = (q >> 1) ? (r0 + 8) : r0;
                float inr = (q >> 1) ? inr8 : inr0;
                float ini = (q >> 1) ? ini8 : ini0;
                int cc = c + (q & 1);
                float mr = acc[mf][nfr][q]     * INV_SCALE;
                float mi = acc[mf][nfr + 4][q] * INV_SCALE;
                atomicAdd(&g_Msg[(size_t)row * 256 + cc],       inr * mr - ini * mi);
                atomicAdd(&g_Msg[(size_t)row * 256 + 128 + cc], inr * mi + ini * mr);
            }
        }
    }
}

// ---------------- K3: MLP GEMM (tf32, fused bias+residual+split) ----------------
#define KT   16
#define SROW 20

__global__ __launch_bounds__(256) void k_gemm_mlp(
    const float* __restrict__ br, const float* __restrict__ bi,
    const float* __restrict__ xr, const float* __restrict__ xi,
    float* __restrict__ out)
{
    __shared__ __align__(16) float As2[2][128 * SROW];
    __shared__ __align__(16) float Bs2[2][128 * SROW];

    const float* A = g_Msg; const float* B = g_Wbig;
    const int lda = 256, ldb = 256, nk = 256 / KT;

    int tid = threadIdx.x;
    int m0 = blockIdx.x * 128;
    int n0 = blockIdx.y * 128;
    const float* Ag = A + (size_t)m0 * lda;
    const float* Bg = B + (size_t)n0 * ldb;

    uint32_t sA = (uint32_t)__cvta_generic_to_shared(&As2[0][0]);
    uint32_t sB = (uint32_t)__cvta_generic_to_shared(&Bs2[0][0]);

    auto load_stage = [&](int buf, int kt) {
        int k0 = kt * KT;
#pragma unroll
        for (int i = 0; i < 2; i++) {
            int v = tid + i * 256;
            int r = v >> 2, c4 = v & 3;
            cp16(sA + (uint32_t)(buf * 128 * SROW + r * SROW + c4 * 4) * 4,
                 Ag + (size_t)r * lda + k0 + c4 * 4);
            cp16(sB + (uint32_t)(buf * 128 * SROW + r * SROW + c4 * 4) * 4,
                 Bg + (size_t)r * ldb + k0 + c4 * 4);
        }
        asm volatile("cp.async.commit_group;\n");
    };

    float acc[2][8][4];
#pragma unroll
    for (int a = 0; a < 2; a++)
#pragma unroll
        for (int b = 0; b < 8; b++)
#pragma unroll
            for (int c = 0; c < 4; c++) acc[a][b][c] = 0.f;

    int wid = tid >> 5, lane = tid & 31;
    int wm = (wid & 3) * 32;
    int wn = (wid >> 2) * 64;
    int g = lane >> 2, tg = lane & 3;

    load_stage(0, 0);
    for (int kt = 0; kt < nk; kt++) {
        if (kt + 1 < nk) {
            load_stage((kt + 1) & 1, kt + 1);
            asm volatile("cp.async.wait_group 1;\n");
        } else {
            asm volatile("cp.async.wait_group 0;\n");
        }
        __syncthreads();
        const float* as = &As2[kt & 1][0];
        const float* bs = &Bs2[kt & 1][0];
#pragma unroll
        for (int k8 = 0; k8 < 2; k8++) {
            uint32_t a[2][4], b[8][2];
#pragma unroll
            for (int mf = 0; mf < 2; mf++) {
                int rb = wm + mf * 16;
                a[mf][0] = __float_as_uint(as[(rb + g)     * SROW + k8 * 8 + tg]);
                a[mf][1] = __float_as_uint(as[(rb + g + 8) * SROW + k8 * 8 + tg]);
                a[mf][2] = __float_as_uint(as[(rb + g)     * SROW + k8 * 8 + tg + 4]);
                a[mf][3] = __float_as_uint(as[(rb + g + 8) * SROW + k8 * 8 + tg + 4]);
            }
#pragma unroll
            for (int nf = 0; nf < 8; nf++) {
                int cb = wn + nf * 8;
                b[nf][0] = __float_as_uint(bs[(cb + g) * SROW + k8 * 8 + tg]);
                b[nf][1] = __float_as_uint(bs[(cb + g) * SROW + k8 * 8 + tg + 4]);
            }
#pragma unroll
            for (int mf = 0; mf < 2; mf++)
#pragma unroll
                for (int nf = 0; nf < 8; nf++) {
                    asm volatile(
                        "mma.sync.aligned.m16n8k8.row.col.f32.tf32.tf32.f32 "
                        "{%0,%1,%2,%3}, {%4,%5,%6,%7}, {%8,%9}, {%0,%1,%2,%3};\n"
                        : "+f"(acc[mf][nf][0]), "+f"(acc[mf][nf][1]),
                          "+f"(acc[mf][nf][2]), "+f"(acc[mf][nf][3])
                        : "r"(a[mf][0]), "r"(a[mf][1]), "r"(a[mf][2]), "r"(a[mf][3]),
                          "r"(b[nf][0]), "r"(b[nf][1]));
                }
        }
        __syncthreads();
    }

#pragma unroll
    for (int mf = 0; mf < 2; mf++)
#pragma unroll
        for (int nf = 0; nf < 8; nf++) {
            int row = m0 + wm + mf * 16 + g;
            int col = n0 + wn + nf * 8 + 2 * tg;
#pragma unroll
            for (int q = 0; q < 4; q++) {
                int r = row + (q >> 1) * 8;
                int c = col + (q & 1);
                float v = acc[mf][nf][q];
                if (c < 128) {
                    out[(size_t)r * 128 + c] =
                        v + br[c] - bi[c] + xr[(size_t)r * 128 + c];
                } else {
                    int cc = c - 128;
                    out[(size_t)ND + (size_t)r * 128 + cc] =
                        v + br[cc] + bi[cc] + xi[(size_t)r * 128 + cc];
                }
            }
        }
}

// ---------------- K4: losses ----------------
__global__ void k_losses(const float* __restrict__ thi,
                         const int* __restrict__ labels,
                         const int* __restrict__ tidx,
                         float* __restrict__ out)
{
    __shared__ float red[256];
    int tid = threadIdx.x;

    if (tid == 0) {
        float st[C_CLS];
        for (int c = 0; c < C_CLS; c++) st[c] = thi[c];
        for (int i = 1; i < C_CLS; i++) {
            float key = st[i]; int k = i - 1;
            while (k >= 0 && st[k] > key) { st[k + 1] = st[k]; k--; }
            st[k + 1] = key;
        }
        float sum = 0.f, mx = 0.f;
        for (int c = 0; c < C_CLS - 1; c++) {
            float d = fabsf(st[c + 1] - st[c]);
            sum += d; if (d > mx) mx = d;
        }
        float difference = sum / (mx + 1e-6f);
        out[(size_t)2 * ND] = 0.1f / (1e-6f + difference);
    }

    float accn = 0.f;
    for (int t = tid; t < T_TRAIN; t += 256) {
        int row = tidx[t];
        int lab = labels[row];
        float l[C_CLS]; float m = -1e30f;
#pragma unroll
        for (int c = 0; c < C_CLS; c++) { l[c] = g_pn[row * C_CLS + c]; m = fmaxf(m, l[c]); }
        float s = 0.f;
#pragma unroll
        for (int c = 0; c < C_CLS; c++) s += expf(l[c] - m);
        float lse = m + logf(s);
        float lp = 0.f;
#pragma unroll
        for (int c = 0; c < C_CLS; c++) if (c == lab) lp = l[c] - lse;
        accn += -lp;
    }
    red[tid] = accn;
    __syncthreads();
    for (int off = 128; off; off >>= 1) {
        if (tid < off) red[tid] += red[tid + off];
        __syncthreads();
    }
    if (tid == 0) out[(size_t)2 * ND + 1] = red[0] / (float)T_TRAIN * 0.1f;
}

// ---------------- launch ----------------
extern "C" void kernel_launch(void* const* d_in, const int* in_sizes, int n_in,
                              void* d_out, int out_size)
{
    const float* x_real     = (const float*)d_in[0];
    const float* x_imag     = (const float*)d_in[1];
    const float* adj        = (const float*)d_in[2];
    const float* theta_real = (const float*)d_in[3];
    const float* theta_imag = (const float*)d_in[4];
    const float* W_r        = (const float*)d_in[5];
    const float* b_r        = (const float*)d_in[6];
    const float* W_i        = (const float*)d_in[7];
    const float* b_i        = (const float*)d_in[8];
    const float* Wc_r       = (const float*)d_in[9];
    const float* bc_r       = (const float*)d_in[10];
    const float* Wc_i       = (const float*)d_in[11];
    const float* bc_i       = (const float*)d_in[12];
    const int*   labels     = (const int*)d_in[13];
    const int*   train_idx  = (const int*)d_in[14];
    float* out = (float*)d_out;

    cudaFuncSetAttribute(k_gemm1, cudaFuncAttributeMaxDynamicSharedMemorySize, SMEM_G1);

    k_zero<<<1024, 512>>>();              // 2M float4 = 8MB
    k_build_wbig<<<256, 256>>>(W_r, W_i);
    k_node_prep<<<1024, 256>>>(x_real, x_imag, Wc_r, Wc_i, bc_r, bc_i,
                               theta_real, theta_imag);
    k_transp<<<dim3(256, 8), dim3(32, 8)>>>();
    k_gemm1<<<dim3(64, 1, NSPLIT), 256, SMEM_G1>>>(adj);
    k_gemm_mlp<<<dim3(64, 2), 256>>>(b_r, b_i, x_real, x_imag, out);
    k_losses<<<1, 256>>>(theta_imag, labels, train_idx, out);
}

// round 12
// speedup vs baseline: 1.2418x; 1.2418x over previous
#include <cuda_runtime.h>
#include <cuda_fp16.h>
#include <cstdint>

#define N_NODES 8192
#define D_FEAT  128
#define C_CLS   10
#define T_TRAIN 1024
#define ND (N_NODES * D_FEAT)

#define INV_SCALE (1.0f / 4096.0f)

// ---------------- scratch (device globals; no allocation allowed) ----------------
__device__ __align__(128) __half g_Sh[N_NODES * 256];    // [s_r|s_i] node-major fp16
__device__ __align__(128) __half g_STh[256 * N_NODES];   // S^T fp16 [256,8192] K-major (GEMM B)
__device__ __align__(128) float  g_P[2 * N_NODES * 256]; // K-split partial sums
__device__ __align__(128) float  g_Msg[N_NODES * 256];   // combined msg [8192,256]
__device__ __align__(128) float  g_in[2 * N_NODES];      // in_r, in_i
__device__ __align__(128) float  g_pn[N_NODES * C_CLS];  // pseudo_norm
__device__ __align__(128) float  g_Wbig[256 * 256];      // [[Wr,-Wi],[Wi,Wr]] K-major

// ---------------- helpers ----------------
__device__ __forceinline__ void cp16(uint32_t smem, const void* g) {
    asm volatile("cp.async.cg.shared.global [%0], [%1], 16;\n" :: "r"(smem), "l"(g));
}
// exact x4096 via exponent add (adj >= 0; 0 stays ~0 after f16 round)
__device__ __forceinline__ uint32_t packh2_scaled(float x, float y) {
    float xs = __uint_as_float(__float_as_uint(x) + 0x06000000u);
    float ys = __uint_as_float(__float_as_uint(y) + 0x06000000u);
    __half2 h = __floats2half2_rn(xs, ys);
    return *reinterpret_cast<uint32_t*>(&h);
}
#define LDSM_X4(r0, r1, r2, r3, addr) \
    asm volatile("ldmatrix.sync.aligned.m8n8.x4.shared.b16 {%0,%1,%2,%3}, [%4];" \
        : "=r"(r0), "=r"(r1), "=r"(r2), "=r"(r3) : "r"(addr))

// ---------------- K1: per-node prep (+ fused Wbig build in extra blocks) ----------------
__global__ __launch_bounds__(256) void k_node_prep(
    const float* __restrict__ xr_g, const float* __restrict__ xi_g,
    const float* __restrict__ Wcr, const float* __restrict__ Wci,
    const float* __restrict__ bcr, const float* __restrict__ bci,
    const float* __restrict__ thr, const float* __restrict__ thi,
    const float* __restrict__ Wr_mlp, const float* __restrict__ Wi_mlp)
{
    if (blockIdx.x >= 1024) {
        // Wbig build: 256 blocks x 256 threads = 65536 elems
        int idx = (blockIdx.x - 1024) * 256 + threadIdx.x;
        int d = idx >> 8, e = idx & 255;
        float v;
        if (d < 128) v = (e < 128) ? Wr_mlp[d * 128 + e] : -Wi_mlp[d * 128 + (e - 128)];
        else {
            int dd = d - 128;
            v = (e < 128) ? Wi_mlp[dd * 128 + e] : Wr_mlp[dd * 128 + (e - 128)];
        }
        g_Wbig[idx] = v;
        return;
    }

    __shared__ float sWr[C_CLS * 128], sWi[C_CLS * 128];
    __shared__ float sb[4 * C_CLS];
    int tid = threadIdx.x;
    for (int i = tid; i < C_CLS * 128; i += 256) { sWr[i] = Wcr[i]; sWi[i] = Wci[i]; }
    if (tid < C_CLS) {
        sb[tid] = bcr[tid]; sb[C_CLS + tid] = bci[tid];
        sb[2 * C_CLS + tid] = thr[tid]; sb[3 * C_CLS + tid] = thi[tid];
    }
    __syncthreads();

    int wid = tid >> 5, lane = tid & 31;
    int j = blockIdx.x * 8 + wid;

    float xr[4], xi[4];
#pragma unroll
    for (int k = 0; k < 4; k++) {
        xr[k] = xr_g[j * 128 + lane + 32 * k];
        xi[k] = xi_g[j * 128 + lane + 32 * k];
    }

    float pn[C_CLS];
#pragma unroll
    for (int c = 0; c < C_CLS; c++) {
        float p1 = 0.f, p2 = 0.f, p3 = 0.f, p4 = 0.f;
#pragma unroll
        for (int k = 0; k < 4; k++) {
            float wr = sWr[c * 128 + lane + 32 * k];
            float wi = sWi[c * 128 + lane + 32 * k];
            p1 += xr[k] * wr; p2 += xi[k] * wr;
            p3 += xi[k] * wi; p4 += xr[k] * wi;
        }
#pragma unroll
        for (int off = 16; off; off >>= 1) {
            p1 += __shfl_xor_sync(0xffffffffu, p1, off);
            p2 += __shfl_xor_sync(0xffffffffu, p2, off);
            p3 += __shfl_xor_sync(0xffffffffu, p3, off);
            p4 += __shfl_xor_sync(0xffffffffu, p4, off);
        }
        float cr = p1 + sb[c] - p3 - sb[C_CLS + c];
        float ci = p2 + sb[c] + p4 + sb[C_CLS + c];
        pn[c] = sqrtf(cr * cr + ci * ci);
    }

    float m = pn[0];
#pragma unroll
    for (int c = 1; c < C_CLS; c++) m = fmaxf(m, pn[c]);
    float s = 0.f, e[C_CLS];
#pragma unroll
    for (int c = 0; c < C_CLS; c++) { e[c] = expf(pn[c] - m); s += e[c]; }
    float inv = 1.0f / s, inr = 0.f, ini = 0.f;
#pragma unroll
    for (int c = 0; c < C_CLS; c++) {
        float sc = e[c] * inv;
        inr += sc * sb[2 * C_CLS + c];
        ini += sc * sb[3 * C_CLS + c];
    }

    if (lane == 0) {
#pragma unroll
        for (int c = 0; c < C_CLS; c++) g_pn[j * C_CLS + c] = pn[c];
        g_in[j] = inr; g_in[N_NODES + j] = ini;
    }

#pragma unroll
    for (int k = 0; k < 4; k++) {
        int d = lane + 32 * k;
        g_Sh[j * 256 + d]       = __float2half(inr * xr[k] + ini * xi[k]);
        g_Sh[j * 256 + 128 + d] = __float2half(inr * xi[k] - ini * xr[k]);
    }
}

// ---------------- K1b: transpose g_Sh [8192,256] -> g_STh [256,8192] ----------------
__global__ void k_transp() {
    __shared__ __half t[32][33];
    int bx = blockIdx.x;
    int by = blockIdx.y;
    int lx = threadIdx.x, ly = threadIdx.y;
#pragma unroll
    for (int i = 0; i < 32; i += 8)
        t[ly + i][lx] = g_Sh[(size_t)(bx * 32 + ly + i) * 256 + by * 32 + lx];
    __syncthreads();
#pragma unroll
    for (int i = 0; i < 32; i += 8)
        g_STh[(size_t)(by * 32 + ly + i) * N_NODES + bx * 32 + lx] = t[lx][ly + i];
}

// ================= GEMM1 (round-10 version): fp16 mma.sync + ldmatrix + fragment DB =================
// 128x256 CTA tile, 8 warps @ 64x64, A: LDG->cvt->STS (2-stage), B: cp.async (4-stage).
#define BM 128
#define BN 256
#define BK 32
#define NSPLIT 2
#define KSPLIT (N_NODES / NSPLIT)    // 4096
#define NKT (KSPLIT / BK)            // 128
#define ASTR 40                      // halfs per A smem row (80B)
#define BSTR 40                      // halfs per B smem row (80B)
#define ASTAGE (BM * ASTR)           // halfs/stage (A, 2 stages)
#define BSTAGE (BN * BSTR)           // halfs/stage (B, 4 stages)
#define SMEM_G1 ((2 * ASTAGE + 4 * BSTAGE) * 2)   // 102400 B

__global__ __launch_bounds__(256, 1) void k_gemm1(const float* __restrict__ adj) {
    extern __shared__ __align__(16) char smraw[];
    __half* Ah = reinterpret_cast<__half*>(smraw);
    __half* Bs = reinterpret_cast<__half*>(smraw + 2 * ASTAGE * 2);

    int tid = threadIdx.x;
    int m0 = blockIdx.x * BM;
    int kb = blockIdx.z * KSPLIT;
    const float*  Ag = adj + (size_t)m0 * N_NODES + kb;
    const __half* Bg = g_STh + kb;

    uint32_t sAh = (uint32_t)__cvta_generic_to_shared(Ah);
    uint32_t sB  = (uint32_t)__cvta_generic_to_shared(Bs);

    // A: thread t handles row r=t>>1, 16 cols starting at (t&1)*16
    int ar = tid >> 1, ac = (tid & 1) * 16;

    float4 pa[4];
    auto ldgA = [&](int kt) {
        const float4* p = reinterpret_cast<const float4*>(
            Ag + (size_t)ar * N_NODES + kt * BK + ac);
#pragma unroll
        for (int i = 0; i < 4; i++) pa[i] = p[i];
    };
    auto stsA = [&](int st) {
        uint32_t d[8];
#pragma unroll
        for (int i = 0; i < 4; i++) {
            d[2 * i]     = packh2_scaled(pa[i].x, pa[i].y);
            d[2 * i + 1] = packh2_scaled(pa[i].z, pa[i].w);
        }
        uint4* dst = reinterpret_cast<uint4*>(Ah + st * ASTAGE + ar * ASTR + ac);
        dst[0] = make_uint4(d[0], d[1], d[2], d[3]);
        dst[1] = make_uint4(d[4], d[5], d[6], d[7]);
    };

    auto loadB = [&](int kt) {
        int st = kt & 3;
        int k0 = kt * BK;
#pragma unroll
        for (int i = 0; i < 4; i++) {               // 1024 vec16 / 256 thr
            int v = tid + i * 256;
            int r = v >> 2, c = v & 3;
            cp16(sB + (uint32_t)(st * BSTAGE + r * BSTR + c * 8) * 2,
                 Bg + (size_t)r * N_NODES + k0 + c * 8);
        }
        asm volatile("cp.async.commit_group;\n");
    };

    float acc[4][8][4];
#pragma unroll
    for (int a = 0; a < 4; a++)
#pragma unroll
        for (int b = 0; b < 8; b++)
#pragma unroll
            for (int c = 0; c < 4; c++) acc[a][b][c] = 0.f;

    int wid = tid >> 5, lane = tid & 31;
    int wm = (wid & 1) * 64;        // warp grid 2(m) x 4(n), warp tile 64x64
    int wn = (wid >> 1) * 64;

    uint32_t Af[2][16], Bf[2][16];

    int a_row = lane & 15, a_half = (lane >> 4) * 8;
    int b_q = lane >> 3, b_r = lane & 7;
    int b_nfo = (b_q >> 1), b_half = (b_q & 1) * 8;

    auto fragload = [&](int buf, int ast, int bst, int k0) {
#pragma unroll
        for (int mf = 0; mf < 4; mf++) {
            uint32_t ad = sAh + (uint32_t)(ast * ASTAGE +
                (wm + mf * 16 + a_row) * ASTR + k0 + a_half) * 2;
            LDSM_X4(Af[buf][mf * 4 + 0], Af[buf][mf * 4 + 1],
                    Af[buf][mf * 4 + 2], Af[buf][mf * 4 + 3], ad);
        }
#pragma unroll
        for (int p = 0; p < 4; p++) {
            int nf = p * 2 + b_nfo;
            uint32_t ad = sB + (uint32_t)(bst * BSTAGE +
                (wn + nf * 8 + b_r) * BSTR + k0 + b_half) * 2;
            LDSM_X4(Bf[buf][p * 4 + 0], Bf[buf][p * 4 + 1],
                    Bf[buf][p * 4 + 2], Bf[buf][p * 4 + 3], ad);
        }
    };

    auto mma_all = [&](int buf) {
#pragma unroll
        for (int nf = 0; nf < 8; nf++) {
            uint32_t b0 = Bf[buf][(nf >> 1) * 4 + (nf & 1) * 2];
            uint32_t b1 = Bf[buf][(nf >> 1) * 4 + (nf & 1) * 2 + 1];
#pragma unroll
            for (int mf = 0; mf < 4; mf++) {
                asm volatile(
                    "mma.sync.aligned.m16n8k16.row.col.f32.f16.f16.f32 "
                    "{%0,%1,%2,%3}, {%4,%5,%6,%7}, {%8,%9}, {%0,%1,%2,%3};\n"
                    : "+f"(acc[mf][nf][0]), "+f"(acc[mf][nf][1]),
                      "+f"(acc[mf][nf][2]), "+f"(acc[mf][nf][3])
                    : "r"(Af[buf][mf * 4 + 0]), "r"(Af[buf][mf * 4 + 1]),
                      "r"(Af[buf][mf * 4 + 2]), "r"(Af[buf][mf * 4 + 3]),
                      "r"(b0), "r"(b1));
            }
        }
    };

    // prologue
    ldgA(0);
    loadB(0); loadB(1); loadB(2);
    stsA(0);
    ldgA(1);
    asm volatile("cp.async.wait_group 2;\n");
    __syncthreads();

    for (int kt = 0; kt < NKT; kt++) {
        if (kt + 3 < NKT) loadB(kt + 3);
        fragload(0, kt & 1, kt & 3, 0);
        fragload(1, kt & 1, kt & 3, 16);
        mma_all(0);
        if (kt + 1 < NKT) {
            stsA((kt + 1) & 1);
            if (kt + 2 < NKT) ldgA(kt + 2);
        }
        mma_all(1);
        if (kt + 1 < NKT) {
            int rem = NKT - 2 - kt;
            if (rem >= 2)      asm volatile("cp.async.wait_group 2;\n");
            else if (rem == 1) asm volatile("cp.async.wait_group 1;\n");
            else               asm volatile("cp.async.wait_group 0;\n");
            __syncthreads();
        }
    }

    // epilogue: raw partial store
    int g = lane >> 2, tg = lane & 3;
    float* P = g_P + (size_t)blockIdx.z * (N_NODES * 256);
#pragma unroll
    for (int mf = 0; mf < 4; mf++)
#pragma unroll
        for (int nf = 0; nf < 8; nf++) {
            int row = m0 + wm + mf * 16 + g;
            int col = wn + nf * 8 + 2 * tg;
            P[(size_t)row * 256 + col]           = acc[mf][nf][0];
            P[(size_t)row * 256 + col + 1]       = acc[mf][nf][1];
            P[(size_t)(row + 8) * 256 + col]     = acc[mf][nf][2];
            P[(size_t)(row + 8) * 256 + col + 1] = acc[mf][nf][3];
        }
}

// ---------------- K2b: msg = diag(in)*(P0+P1)/SCALE, vectorized; + fused losses block ----------------
__global__ void k_combine2(const float* __restrict__ thi,
                           const int* __restrict__ labels,
                           const int* __restrict__ tidx,
                           float* __restrict__ out)
{
    if (blockIdx.x == 1024) {
        // ---- losses (one block) ----
        __shared__ float red[256];
        int tid = threadIdx.x;

        if (tid == 0) {
            float st[C_CLS];
            for (int c = 0; c < C_CLS; c++) st[c] = thi[c];
            for (int i = 1; i < C_CLS; i++) {
                float key = st[i]; int k = i - 1;
                while (k >= 0 && st[k] > key) { st[k + 1] = st[k]; k--; }
                st[k + 1] = key;
            }
            float sum = 0.f, mx = 0.f;
            for (int c = 0; c < C_CLS - 1; c++) {
                float d = fabsf(st[c + 1] - st[c]);
                sum += d; if (d > mx) mx = d;
            }
            float difference = sum / (mx + 1e-6f);
            out[(size_t)2 * ND] = 0.1f / (1e-6f + difference);
        }

        float accn = 0.f;
        for (int t = tid; t < T_TRAIN; t += 256) {
            int row = tidx[t];
            int lab = labels[row];
            float l[C_CLS]; float m = -1e30f;
#pragma unroll
            for (int c = 0; c < C_CLS; c++) { l[c] = g_pn[row * C_CLS + c]; m = fmaxf(m, l[c]); }
            float s = 0.f;
#pragma unroll
            for (int c = 0; c < C_CLS; c++) s += expf(l[c] - m);
            float lse = m + logf(s);
            float lp = 0.f;
#pragma unroll
            for (int c = 0; c < C_CLS; c++) if (c == lab) lp = l[c] - lse;
            accn += -lp;
        }
        red[tid] = accn;
        __syncthreads();
        for (int off = 128; off; off >>= 1) {
            if (tid < off) red[tid] += red[tid + off];
            __syncthreads();
        }
        if (tid == 0) out[(size_t)2 * ND + 1] = red[0] / (float)T_TRAIN * 0.1f;
        return;
    }

    // ---- combine, 4 elems/thread ----
    int t = blockIdx.x * 256 + threadIdx.x;   // 262144 threads
    int n = t >> 5, d0 = (t & 31) * 4;
    size_t b = (size_t)n * 256;
    const size_t PS = (size_t)N_NODES * 256;
    float4 r0 = *reinterpret_cast<const float4*>(&g_P[b + d0]);
    float4 r1 = *reinterpret_cast<const float4*>(&g_P[PS + b + d0]);
    float4 i0 = *reinterpret_cast<const float4*>(&g_P[b + 128 + d0]);
    float4 i1 = *reinterpret_cast<const float4*>(&g_P[PS + b + 128 + d0]);
    float inr = g_in[n], ini = g_in[N_NODES + n];
    float4 vr, vi;
#pragma unroll
    for (int q = 0; q < 4; q++) {
        float mr = ((&r0.x)[q] + (&r1.x)[q]) * INV_SCALE;
        float mi = ((&i0.x)[q] + (&i1.x)[q]) * INV_SCALE;
        (&vr.x)[q] = inr * mr - ini * mi;
        (&vi.x)[q] = inr * mi + ini * mr;
    }
    *reinterpret_cast<float4*>(&g_Msg[b + d0])       = vr;
    *reinterpret_cast<float4*>(&g_Msg[b + 128 + d0]) = vi;
}

// ---------------- K3: MLP GEMM (tf32, fused bias+residual+split) ----------------
#define KT   16
#define SROW 20

__global__ __launch_bounds__(256) void k_gemm_mlp(
    const float* __restrict__ br, const float* __restrict__ bi,
    const float* __restrict__ xr, const float* __restrict__ xi,
    float* __restrict__ out)
{
    __shared__ __align__(16) float As2[2][128 * SROW];
    __shared__ __align__(16) float Bs2[2][128 * SROW];

    const float* A = g_Msg; const float* B = g_Wbig;
    const int lda = 256, ldb = 256, nk = 256 / KT;

    int tid = threadIdx.x;
    int m0 = blockIdx.x * 128;
    int n0 = blockIdx.y * 128;
    const float* Ag = A + (size_t)m0 * lda;
    const float* Bg = B + (size_t)n0 * ldb;

    uint32_t sA = (uint32_t)__cvta_generic_to_shared(&As2[0][0]);
    uint32_t sB = (uint32_t)__cvta_generic_to_shared(&Bs2[0][0]);

    auto load_stage = [&](int buf, int kt) {
        int k0 = kt * KT;
#pragma unroll
        for (int i = 0; i < 2; i++) {
            int v = tid + i * 256;
            int r = v >> 2, c4 = v & 3;
            cp16(sA + (uint32_t)(buf * 128 * SROW + r * SROW + c4 * 4) * 4,
                 Ag + (size_t)r * lda + k0 + c4 * 4);
            cp16(sB + (uint32_t)(buf * 128 * SROW + r * SROW + c4 * 4) * 4,
                 Bg + (size_t)r * ldb + k0 + c4 * 4);
        }
        asm volatile("cp.async.commit_group;\n");
    };

    float acc[2][8][4];
#pragma unroll
    for (int a = 0; a < 2; a++)
#pragma unroll
        for (int b = 0; b < 8; b++)
#pragma unroll
            for (int c = 0; c < 4; c++) acc[a][b][c] = 0.f;

    int wid = tid >> 5, lane = tid & 31;
    int wm = (wid & 3) * 32;
    int wn = (wid >> 2) * 64;
    int g = lane >> 2, tg = lane & 3;

    load_stage(0, 0);
    for (int kt = 0; kt < nk; kt++) {
        if (kt + 1 < nk) {
            load_stage((kt + 1) & 1, kt + 1);
            asm volatile("cp.async.wait_group 1;\n");
        } else {
            asm volatile("cp.async.wait_group 0;\n");
        }
        __syncthreads();
        const float* as = &As2[kt & 1][0];
        const float* bs = &Bs2[kt & 1][0];
#pragma unroll
        for (int k8 = 0; k8 < 2; k8++) {
            uint32_t a[2][4], b[8][2];
#pragma unroll
            for (int mf = 0; mf < 2; mf++) {
                int rb = wm + mf * 16;
                a[mf][0] = __float_as_uint(as[(rb + g)     * SROW + k8 * 8 + tg]);
                a[mf][1] = __float_as_uint(as[(rb + g + 8) * SROW + k8 * 8 + tg]);
                a[mf][2] = __float_as_uint(as[(rb + g)     * SROW + k8 * 8 + tg + 4]);
                a[mf][3] = __float_as_uint(as[(rb + g + 8) * SROW + k8 * 8 + tg + 4]);
            }
#pragma unroll
            for (int nf = 0; nf < 8; nf++) {
                int cb = wn + nf * 8;
                b[nf][0] = __float_as_uint(bs[(cb + g) * SROW + k8 * 8 + tg]);
                b[nf][1] = __float_as_uint(bs[(cb + g) * SROW + k8 * 8 + tg + 4]);
            }
#pragma unroll
            for (int mf = 0; mf < 2; mf++)
#pragma unroll
                for (int nf = 0; nf < 8; nf++) {
                    asm volatile(
                        "mma.sync.aligned.m16n8k8.row.col.f32.tf32.tf32.f32 "
                        "{%0,%1,%2,%3}, {%4,%5,%6,%7}, {%8,%9}, {%0,%1,%2,%3};\n"
                        : "+f"(acc[mf][nf][0]), "+f"(acc[mf][nf][1]),
                          "+f"(acc[mf][nf][2]), "+f"(acc[mf][nf][3])
                        : "r"(a[mf][0]), "r"(a[mf][1]), "r"(a[mf][2]), "r"(a[mf][3]),
                          "r"(b[nf][0]), "r"(b[nf][1]));
                }
        }
        __syncthreads();
    }

#pragma unroll
    for (int mf = 0; mf < 2; mf++)
#pragma unroll
        for (int nf = 0; nf < 8; nf++) {
            int row = m0 + wm + mf * 16 + g;
            int col = n0 + wn + nf * 8 + 2 * tg;
#pragma unroll
            for (int q = 0; q < 4; q++) {
                int r = row + (q >> 1) * 8;
                int c = col + (q & 1);
                float v = acc[mf][nf][q];
                if (c < 128) {
                    out[(size_t)r * 128 + c] =
                        v + br[c] - bi[c] + xr[(size_t)r * 128 + c];
                } else {
                    int cc = c - 128;
                    out[(size_t)ND + (size_t)r * 128 + cc] =
                        v + br[cc] + bi[cc] + xi[(size_t)r * 128 + cc];
                }
            }
        }
}

// ---------------- launch ----------------
extern "C" void kernel_launch(void* const* d_in, const int* in_sizes, int n_in,
                              void* d_out, int out_size)
{
    const float* x_real     = (const float*)d_in[0];
    const float* x_imag     = (const float*)d_in[1];
    const float* adj        = (const float*)d_in[2];
    const float* theta_real = (const float*)d_in[3];
    const float* theta_imag = (const float*)d_in[4];
    const float* W_r        = (const float*)d_in[5];
    const float* b_r        = (const float*)d_in[6];
    const float* W_i        = (const float*)d_in[7];
    const float* b_i        = (const float*)d_in[8];
    const float* Wc_r       = (const float*)d_in[9];
    const float* bc_r       = (const float*)d_in[10];
    const float* Wc_i       = (const float*)d_in[11];
    const float* bc_i       = (const float*)d_in[12];
    const int*   labels     = (const int*)d_in[13];
    const int*   train_idx  = (const int*)d_in[14];
    float* out = (float*)d_out;

    cudaFuncSetAttribute(k_gemm1, cudaFuncAttributeMaxDynamicSharedMemorySize, SMEM_G1);

    k_node_prep<<<1280, 256>>>(x_real, x_imag, Wc_r, Wc_i, bc_r, bc_i,
                               theta_real, theta_imag, W_r, W_i);
    k_transp<<<dim3(256, 8), dim3(32, 8)>>>();
    k_gemm1<<<dim3(64, 1, NSPLIT), 256, SMEM_G1>>>(adj);
    k_combine2<<<1025, 256>>>(theta_imag, labels, train_idx, out);
    k_gemm_mlp<<<dim3(64, 2), 256>>>(b_r, b_i, x_real, x_imag, out);
}

// round 13
// speedup vs baseline: 1.2775x; 1.0288x over previous
#include <cuda_runtime.h>
#include <cuda_fp16.h>
#include <cstdint>

#define N_NODES 8192
#define D_FEAT  128
#define C_CLS   10
#define T_TRAIN 1024
#define ND (N_NODES * D_FEAT)

#define INV_SCALE (1.0f / 4096.0f)

// ---------------- scratch (device globals; no allocation allowed) ----------------
__device__ __align__(128) __half g_Sh[N_NODES * 256];    // [s_r|s_i] node-major fp16
__device__ __align__(128) __half g_STh[256 * N_NODES];   // S^T fp16 [256,8192] K-major (GEMM B)
__device__ __align__(128) float  g_P[2 * N_NODES * 256]; // K-split partial sums
__device__ __align__(128) __half g_Msgh[N_NODES * 256];  // combined msg fp16 [8192,256]
__device__ __align__(128) float  g_in[2 * N_NODES];      // in_r, in_i
__device__ __align__(128) float  g_pn[N_NODES * C_CLS];  // pseudo_norm
__device__ __align__(128) __half g_Wbigh[256 * 256];     // [[Wr,-Wi],[Wi,Wr]] K-major fp16

// ---------------- helpers ----------------
__device__ __forceinline__ void cp16(uint32_t smem, const void* g) {
    asm volatile("cp.async.cg.shared.global [%0], [%1], 16;\n" :: "r"(smem), "l"(g));
}
// exact x4096 via exponent add (adj >= 0; 0 stays ~0 after f16 round)
__device__ __forceinline__ uint32_t packh2_scaled(float x, float y) {
    float xs = __uint_as_float(__float_as_uint(x) + 0x06000000u);
    float ys = __uint_as_float(__float_as_uint(y) + 0x06000000u);
    __half2 h = __floats2half2_rn(xs, ys);
    return *reinterpret_cast<uint32_t*>(&h);
}
#define LDSM_X4(r0, r1, r2, r3, addr) \
    asm volatile("ldmatrix.sync.aligned.m8n8.x4.shared.b16 {%0,%1,%2,%3}, [%4];" \
        : "=r"(r0), "=r"(r1), "=r"(r2), "=r"(r3) : "r"(addr))

// ---------------- K1: per-node prep (+ fused fp16 Wbig build in extra blocks) ----------------
__global__ __launch_bounds__(256) void k_node_prep(
    const float* __restrict__ xr_g, const float* __restrict__ xi_g,
    const float* __restrict__ Wcr, const float* __restrict__ Wci,
    const float* __restrict__ bcr, const float* __restrict__ bci,
    const float* __restrict__ thr, const float* __restrict__ thi,
    const float* __restrict__ Wr_mlp, const float* __restrict__ Wi_mlp)
{
    if (blockIdx.x >= 1024) {
        int idx = (blockIdx.x - 1024) * 256 + threadIdx.x;
        int d = idx >> 8, e = idx & 255;
        float v;
        if (d < 128) v = (e < 128) ? Wr_mlp[d * 128 + e] : -Wi_mlp[d * 128 + (e - 128)];
        else {
            int dd = d - 128;
            v = (e < 128) ? Wi_mlp[dd * 128 + e] : Wr_mlp[dd * 128 + (e - 128)];
        }
        g_Wbigh[idx] = __float2half(v);
        return;
    }

    __shared__ float sWr[C_CLS * 128], sWi[C_CLS * 128];
    __shared__ float sb[4 * C_CLS];
    int tid = threadIdx.x;
    for (int i = tid; i < C_CLS * 128; i += 256) { sWr[i] = Wcr[i]; sWi[i] = Wci[i]; }
    if (tid < C_CLS) {
        sb[tid] = bcr[tid]; sb[C_CLS + tid] = bci[tid];
        sb[2 * C_CLS + tid] = thr[tid]; sb[3 * C_CLS + tid] = thi[tid];
    }
    __syncthreads();

    int wid = tid >> 5, lane = tid & 31;
    int j = blockIdx.x * 8 + wid;

    float xr[4], xi[4];
#pragma unroll
    for (int k = 0; k < 4; k++) {
        xr[k] = xr_g[j * 128 + lane + 32 * k];
        xi[k] = xi_g[j * 128 + lane + 32 * k];
    }

    float pn[C_CLS];
#pragma unroll
    for (int c = 0; c < C_CLS; c++) {
        float p1 = 0.f, p2 = 0.f, p3 = 0.f, p4 = 0.f;
#pragma unroll
        for (int k = 0; k < 4; k++) {
            float wr = sWr[c * 128 + lane + 32 * k];
            float wi = sWi[c * 128 + lane + 32 * k];
            p1 += xr[k] * wr; p2 += xi[k] * wr;
            p3 += xi[k] * wi; p4 += xr[k] * wi;
        }
#pragma unroll
        for (int off = 16; off; off >>= 1) {
            p1 += __shfl_xor_sync(0xffffffffu, p1, off);
            p2 += __shfl_xor_sync(0xffffffffu, p2, off);
            p3 += __shfl_xor_sync(0xffffffffu, p3, off);
            p4 += __shfl_xor_sync(0xffffffffu, p4, off);
        }
        float cr = p1 + sb[c] - p3 - sb[C_CLS + c];
        float ci = p2 + sb[c] + p4 + sb[C_CLS + c];
        pn[c] = sqrtf(cr * cr + ci * ci);
    }

    float m = pn[0];
#pragma unroll
    for (int c = 1; c < C_CLS; c++) m = fmaxf(m, pn[c]);
    float s = 0.f, e[C_CLS];
#pragma unroll
    for (int c = 0; c < C_CLS; c++) { e[c] = expf(pn[c] - m); s += e[c]; }
    float inv = 1.0f / s, inr = 0.f, ini = 0.f;
#pragma unroll
    for (int c = 0; c < C_CLS; c++) {
        float sc = e[c] * inv;
        inr += sc * sb[2 * C_CLS + c];
        ini += sc * sb[3 * C_CLS + c];
    }

    if (lane == 0) {
#pragma unroll
        for (int c = 0; c < C_CLS; c++) g_pn[j * C_CLS + c] = pn[c];
        g_in[j] = inr; g_in[N_NODES + j] = ini;
    }

#pragma unroll
    for (int k = 0; k < 4; k++) {
        int d = lane + 32 * k;
        g_Sh[j * 256 + d]       = __float2half(inr * xr[k] + ini * xi[k]);
        g_Sh[j * 256 + 128 + d] = __float2half(inr * xi[k] - ini * xr[k]);
    }
}

// ---------------- K1b: transpose + fused losses (extra block column) ----------------
__global__ void k_transp(const float* __restrict__ thi,
                         const int* __restrict__ labels,
                         const int* __restrict__ tidx,
                         float* __restrict__ out)
{
    if (blockIdx.x == 256) {
        if (blockIdx.y != 0) return;
        // ---- losses (one block of 256 threads) ----
        __shared__ float red[256];
        int tid = threadIdx.y * 32 + threadIdx.x;

        if (tid == 0) {
            float st[C_CLS];
            for (int c = 0; c < C_CLS; c++) st[c] = thi[c];
            for (int i = 1; i < C_CLS; i++) {
                float key = st[i]; int k = i - 1;
                while (k >= 0 && st[k] > key) { st[k + 1] = st[k]; k--; }
                st[k + 1] = key;
            }
            float sum = 0.f, mx = 0.f;
            for (int c = 0; c < C_CLS - 1; c++) {
                float d = fabsf(st[c + 1] - st[c]);
                sum += d; if (d > mx) mx = d;
            }
            float difference = sum / (mx + 1e-6f);
            out[(size_t)2 * ND] = 0.1f / (1e-6f + difference);
        }

        float accn = 0.f;
        for (int t = tid; t < T_TRAIN; t += 256) {
            int row = tidx[t];
            int lab = labels[row];
            float l[C_CLS]; float m = -1e30f;
#pragma unroll
            for (int c = 0; c < C_CLS; c++) { l[c] = g_pn[row * C_CLS + c]; m = fmaxf(m, l[c]); }
            float s = 0.f;
#pragma unroll
            for (int c = 0; c < C_CLS; c++) s += expf(l[c] - m);
            float lse = m + logf(s);
            float lp = 0.f;
#pragma unroll
            for (int c = 0; c < C_CLS; c++) if (c == lab) lp = l[c] - lse;
            accn += -lp;
        }
        red[tid] = accn;
        __syncthreads();
        for (int off = 128; off; off >>= 1) {
            if (tid < off) red[tid] += red[tid + off];
            __syncthreads();
        }
        if (tid == 0) out[(size_t)2 * ND + 1] = red[0] / (float)T_TRAIN * 0.1f;
        return;
    }

    __shared__ __half t[32][33];
    int bx = blockIdx.x;
    int by = blockIdx.y;
    int lx = threadIdx.x, ly = threadIdx.y;
#pragma unroll
    for (int i = 0; i < 32; i += 8)
        t[ly + i][lx] = g_Sh[(size_t)(bx * 32 + ly + i) * 256 + by * 32 + lx];
    __syncthreads();
#pragma unroll
    for (int i = 0; i < 32; i += 8)
        g_STh[(size_t)(by * 32 + ly + i) * N_NODES + bx * 32 + lx] = t[lx][ly + i];
}

// ================= GEMM1 (round-10 version, best measured): fp16 mma + ldmatrix + frag DB =================
#define BM 128
#define BN 256
#define BK 32
#define NSPLIT 2
#define KSPLIT (N_NODES / NSPLIT)    // 4096
#define NKT (KSPLIT / BK)            // 128
#define ASTR 40                      // halfs per A smem row (80B)
#define BSTR 40                      // halfs per B smem row (80B)
#define ASTAGE (BM * ASTR)
#define BSTAGE (BN * BSTR)
#define SMEM_G1 ((2 * ASTAGE + 4 * BSTAGE) * 2)   // 102400 B

__global__ __launch_bounds__(256, 1) void k_gemm1(const float* __restrict__ adj) {
    extern __shared__ __align__(16) char smraw[];
    __half* Ah = reinterpret_cast<__half*>(smraw);
    __half* Bs = reinterpret_cast<__half*>(smraw + 2 * ASTAGE * 2);

    int tid = threadIdx.x;
    int m0 = blockIdx.x * BM;
    int kb = blockIdx.z * KSPLIT;
    const float*  Ag = adj + (size_t)m0 * N_NODES + kb;
    const __half* Bg = g_STh + kb;

    uint32_t sAh = (uint32_t)__cvta_generic_to_shared(Ah);
    uint32_t sB  = (uint32_t)__cvta_generic_to_shared(Bs);

    int ar = tid >> 1, ac = (tid & 1) * 16;

    float4 pa[4];
    auto ldgA = [&](int kt) {
        const float4* p = reinterpret_cast<const float4*>(
            Ag + (size_t)ar * N_NODES + kt * BK + ac);
#pragma unroll
        for (int i = 0; i < 4; i++) pa[i] = p[i];
    };
    auto stsA = [&](int st) {
        uint32_t d[8];
#pragma unroll
        for (int i = 0; i < 4; i++) {
            d[2 * i]     = packh2_scaled(pa[i].x, pa[i].y);
            d[2 * i + 1] = packh2_scaled(pa[i].z, pa[i].w);
        }
        uint4* dst = reinterpret_cast<uint4*>(Ah + st * ASTAGE + ar * ASTR + ac);
        dst[0] = make_uint4(d[0], d[1], d[2], d[3]);
        dst[1] = make_uint4(d[4], d[5], d[6], d[7]);
    };

    auto loadB = [&](int kt) {
        int st = kt & 3;
        int k0 = kt * BK;
#pragma unroll
        for (int i = 0; i < 4; i++) {
            int v = tid + i * 256;
            int r = v >> 2, c = v & 3;
            cp16(sB + (uint32_t)(st * BSTAGE + r * BSTR + c * 8) * 2,
                 Bg + (size_t)r * N_NODES + k0 + c * 8);
        }
        asm volatile("cp.async.commit_group;\n");
    };

    float acc[4][8][4];
#pragma unroll
    for (int a = 0; a < 4; a++)
#pragma unroll
        for (int b = 0; b < 8; b++)
#pragma unroll
            for (int c = 0; c < 4; c++) acc[a][b][c] = 0.f;

    int wid = tid >> 5, lane = tid & 31;
    int wm = (wid & 1) * 64;
    int wn = (wid >> 1) * 64;

    uint32_t Af[2][16], Bf[2][16];

    int a_row = lane & 15, a_half = (lane >> 4) * 8;
    int b_q = lane >> 3, b_r = lane & 7;
    int b_nfo = (b_q >> 1), b_half = (b_q & 1) * 8;

    auto fragload = [&](int buf, int ast, int bst, int k0) {
#pragma unroll
        for (int mf = 0; mf < 4; mf++) {
            uint32_t ad = sAh + (uint32_t)(ast * ASTAGE +
                (wm + mf * 16 + a_row) * ASTR + k0 + a_half) * 2;
            LDSM_X4(Af[buf][mf * 4 + 0], Af[buf][mf * 4 + 1],
                    Af[buf][mf * 4 + 2], Af[buf][mf * 4 + 3], ad);
        }
#pragma unroll
        for (int p = 0; p < 4; p++) {
            int nf = p * 2 + b_nfo;
            uint32_t ad = sB + (uint32_t)(bst * BSTAGE +
                (wn + nf * 8 + b_r) * BSTR + k0 + b_half) * 2;
            LDSM_X4(Bf[buf][p * 4 + 0], Bf[buf][p * 4 + 1],
                    Bf[buf][p * 4 + 2], Bf[buf][p * 4 + 3], ad);
        }
    };

    auto mma_all = [&](int buf) {
#pragma unroll
        for (int nf = 0; nf < 8; nf++) {
            uint32_t b0 = Bf[buf][(nf >> 1) * 4 + (nf & 1) * 2];
            uint32_t b1 = Bf[buf][(nf >> 1) * 4 + (nf & 1) * 2 + 1];
#pragma unroll
            for (int mf = 0; mf < 4; mf++) {
                asm volatile(
                    "mma.sync.aligned.m16n8k16.row.col.f32.f16.f16.f32 "
                    "{%0,%1,%2,%3}, {%4,%5,%6,%7}, {%8,%9}, {%0,%1,%2,%3};\n"
                    : "+f"(acc[mf][nf][0]), "+f"(acc[mf][nf][1]),
                      "+f"(acc[mf][nf][2]), "+f"(acc[mf][nf][3])
                    : "r"(Af[buf][mf * 4 + 0]), "r"(Af[buf][mf * 4 + 1]),
                      "r"(Af[buf][mf * 4 + 2]), "r"(Af[buf][mf * 4 + 3]),
                      "r"(b0), "r"(b1));
            }
        }
    };

    ldgA(0);
    loadB(0); loadB(1); loadB(2);
    stsA(0);
    ldgA(1);
    asm volatile("cp.async.wait_group 2;\n");
    __syncthreads();

    for (int kt = 0; kt < NKT; kt++) {
        if (kt + 3 < NKT) loadB(kt + 3);
        fragload(0, kt & 1, kt & 3, 0);
        fragload(1, kt & 1, kt & 3, 16);
        mma_all(0);
        if (kt + 1 < NKT) {
            stsA((kt + 1) & 1);
            if (kt + 2 < NKT) ldgA(kt + 2);
        }
        mma_all(1);
        if (kt + 1 < NKT) {
            int rem = NKT - 2 - kt;
            if (rem >= 2)      asm volatile("cp.async.wait_group 2;\n");
            else if (rem == 1) asm volatile("cp.async.wait_group 1;\n");
            else               asm volatile("cp.async.wait_group 0;\n");
            __syncthreads();
        }
    }

    int g = lane >> 2, tg = lane & 3;
    float* P = g_P + (size_t)blockIdx.z * (N_NODES * 256);
#pragma unroll
    for (int mf = 0; mf < 4; mf++)
#pragma unroll
        for (int nf = 0; nf < 8; nf++) {
            int row = m0 + wm + mf * 16 + g;
            int col = wn + nf * 8 + 2 * tg;
            P[(size_t)row * 256 + col]           = acc[mf][nf][0];
            P[(size_t)row * 256 + col + 1]       = acc[mf][nf][1];
            P[(size_t)(row + 8) * 256 + col]     = acc[mf][nf][2];
            P[(size_t)(row + 8) * 256 + col + 1] = acc[mf][nf][3];
        }
}

// ---------------- K2b: msg = diag(in)*(P0+P1)/SCALE -> fp16, vectorized ----------------
__global__ void k_combine2() {
    int t = blockIdx.x * 256 + threadIdx.x;   // 262144 threads
    int n = t >> 5, d0 = (t & 31) * 4;
    size_t b = (size_t)n * 256;
    const size_t PS = (size_t)N_NODES * 256;
    float4 r0 = *reinterpret_cast<const float4*>(&g_P[b + d0]);
    float4 r1 = *reinterpret_cast<const float4*>(&g_P[PS + b + d0]);
    float4 i0 = *reinterpret_cast<const float4*>(&g_P[b + 128 + d0]);
    float4 i1 = *reinterpret_cast<const float4*>(&g_P[PS + b + 128 + d0]);
    float inr = g_in[n], ini = g_in[N_NODES + n];
    float vr[4], vi[4];
#pragma unroll
    for (int q = 0; q < 4; q++) {
        float mr = ((&r0.x)[q] + (&r1.x)[q]) * INV_SCALE;
        float mi = ((&i0.x)[q] + (&i1.x)[q]) * INV_SCALE;
        vr[q] = inr * mr - ini * mi;
        vi[q] = inr * mi + ini * mr;
    }
    __half2 hr0 = __floats2half2_rn(vr[0], vr[1]);
    __half2 hr1 = __floats2half2_rn(vr[2], vr[3]);
    __half2 hi0 = __floats2half2_rn(vi[0], vi[1]);
    __half2 hi1 = __floats2half2_rn(vi[2], vi[3]);
    *reinterpret_cast<uint2*>(&g_Msgh[b + d0]) =
        make_uint2(*reinterpret_cast<uint32_t*>(&hr0), *reinterpret_cast<uint32_t*>(&hr1));
    *reinterpret_cast<uint2*>(&g_Msgh[b + 128 + d0]) =
        make_uint2(*reinterpret_cast<uint32_t*>(&hi0), *reinterpret_cast<uint32_t*>(&hi1));
}

// ---------------- K3: MLP GEMM (fp16 m16n8k16, fused bias+residual+split) ----------------
#define KT2  32
#define MSTR 40   // halfs per smem row (80B)

__global__ __launch_bounds__(256) void k_gemm_mlp(
    const float* __restrict__ br, const float* __restrict__ bi,
    const float* __restrict__ xr, const float* __restrict__ xi,
    float* __restrict__ out)
{
    __shared__ __align__(16) __half As2[2][128 * MSTR];
    __shared__ __align__(16) __half Bs2[2][128 * MSTR];

    const int nk = 256 / KT2;   // 8

    int tid = threadIdx.x;
    int m0 = blockIdx.x * 128;
    int n0 = blockIdx.y * 128;
    const __half* Ag = g_Msgh + (size_t)m0 * 256;
    const __half* Bg = g_Wbigh + (size_t)n0 * 256;

    uint32_t sA = (uint32_t)__cvta_generic_to_shared(&As2[0][0]);
    uint32_t sB = (uint32_t)__cvta_generic_to_shared(&Bs2[0][0]);

    auto load_stage = [&](int buf, int kt) {
        int k0 = kt * KT2;
#pragma unroll
        for (int i = 0; i < 2; i++) {        // 512 vec16 per operand, 256 thr
            int v = tid + i * 256;
            int r = v >> 2, c = v & 3;
            cp16(sA + (uint32_t)(buf * 128 * MSTR + r * MSTR + c * 8) * 2,
                 Ag + (size_t)r * 256 + k0 + c * 8);
            cp16(sB + (uint32_t)(buf * 128 * MSTR + r * MSTR + c * 8) * 2,
                 Bg + (size_t)r * 256 + k0 + c * 8);
        }
        asm volatile("cp.async.commit_group;\n");
    };

    float acc[2][8][4];
#pragma unroll
    for (int a = 0; a < 2; a++)
#pragma unroll
        for (int b = 0; b < 8; b++)
#pragma unroll
            for (int c = 0; c < 4; c++) acc[a][b][c] = 0.f;

    int wid = tid >> 5, lane = tid & 31;
    int wm = (wid & 3) * 32;   // 4 m-groups x 2 n-groups, warp tile 32x64
    int wn = (wid >> 2) * 64;
    int g = lane >> 2, tg = lane & 3;

    load_stage(0, 0);
    for (int kt = 0; kt < nk; kt++) {
        if (kt + 1 < nk) {
            load_stage((kt + 1) & 1, kt + 1);
            asm volatile("cp.async.wait_group 1;\n");
        } else {
            asm volatile("cp.async.wait_group 0;\n");
        }
        __syncthreads();
        const __half* as = &As2[kt & 1][0];
        const __half* bs = &Bs2[kt & 1][0];
#pragma unroll
        for (int kk = 0; kk < 2; kk++) {
            int k0 = kk * 16;
            uint32_t a[2][4], b[8][2];
#pragma unroll
            for (int mf = 0; mf < 2; mf++) {
                int rb = wm + mf * 16;
                const __half* p0 = as + (rb + g) * MSTR + k0 + 2 * tg;
                const __half* p1 = p0 + 8 * MSTR;
                a[mf][0] = *reinterpret_cast<const uint32_t*>(p0);
                a[mf][1] = *reinterpret_cast<const uint32_t*>(p1);
                a[mf][2] = *reinterpret_cast<const uint32_t*>(p0 + 8);
                a[mf][3] = *reinterpret_cast<const uint32_t*>(p1 + 8);
            }
#pragma unroll
            for (int nf = 0; nf < 8; nf++) {
                int nr = wn + nf * 8 + g;
                b[nf][0] = *reinterpret_cast<const uint32_t*>(bs + nr * MSTR + k0 + 2 * tg);
                b[nf][1] = *reinterpret_cast<const uint32_t*>(bs + nr * MSTR + k0 + 2 * tg + 8);
            }
#pragma unroll
            for (int mf = 0; mf < 2; mf++)
#pragma unroll
                for (int nf = 0; nf < 8; nf++) {
                    asm volatile(
                        "mma.sync.aligned.m16n8k16.row.col.f32.f16.f16.f32 "
                        "{%0,%1,%2,%3}, {%4,%5,%6,%7}, {%8,%9}, {%0,%1,%2,%3};\n"
                        : "+f"(acc[mf][nf][0]), "+f"(acc[mf][nf][1]),
                          "+f"(acc[mf][nf][2]), "+f"(acc[mf][nf][3])
                        : "r"(a[mf][0]), "r"(a[mf][1]), "r"(a[mf][2]), "r"(a[mf][3]),
                          "r"(b[nf][0]), "r"(b[nf][1]));
                }
        }
        __syncthreads();
    }

#pragma unroll
    for (int mf = 0; mf < 2; mf++)
#pragma unroll
        for (int nf = 0; nf < 8; nf++) {
            int row = m0 + wm + mf * 16 + g;
            int col = n0 + wn + nf * 8 + 2 * tg;
#pragma unroll
            for (int q = 0; q < 4; q++) {
                int r = row + (q >> 1) * 8;
                int c = col + (q & 1);
                float v = acc[mf][nf][q];
                if (c < 128) {
                    out[(size_t)r * 128 + c] =
                        v + br[c] - bi[c] + xr[(size_t)r * 128 + c];
                } else {
                    int cc = c - 128;
                    out[(size_t)ND + (size_t)r * 128 + cc] =
                        v + br[cc] + bi[cc] + xi[(size_t)r * 128 + cc];
                }
            }
        }
}

// ---------------- launch ----------------
extern "C" void kernel_launch(void* const* d_in, const int* in_sizes, int n_in,
                              void* d_out, int out_size)
{
    const float* x_real     = (const float*)d_in[0];
    const float* x_imag     = (const float*)d_in[1];
    const float* adj        = (const float*)d_in[2];
    const float* theta_real = (const float*)d_in[3];
    const float* theta_imag = (const float*)d_in[4];
    const float* W_r        = (const float*)d_in[5];
    const float* b_r        = (const float*)d_in[6];
    const float* W_i        = (const float*)d_in[7];
    const float* b_i        = (const float*)d_in[8];
    const float* Wc_r       = (const float*)d_in[9];
    const float* bc_r       = (const float*)d_in[10];
    const float* Wc_i       = (const float*)d_in[11];
    const float* bc_i       = (const float*)d_in[12];
    const int*   labels     = (const int*)d_in[13];
    const int*   train_idx  = (const int*)d_in[14];
    float* out = (float*)d_out;

    cudaFuncSetAttribute(k_gemm1, cudaFuncAttributeMaxDynamicSharedMemorySize, SMEM_G1);

    k_node_prep<<<1280, 256>>>(x_real, x_imag, Wc_r, Wc_i, bc_r, bc_i,
                               theta_real, theta_imag, W_r, W_i);
    k_transp<<<dim3(257, 8), dim3(32, 8)>>>(theta_imag, labels, train_idx, out);
    k_gemm1<<<dim3(64, 1, NSPLIT), 256, SMEM_G1>>>(adj);
    k_combine2<<<1024, 256>>>();
    k_gemm_mlp<<<dim3(64, 2), 256>>>(b_r, b_i, x_real, x_imag, out);
}

// round 14
// speedup vs baseline: 1.2912x; 1.0107x over previous
#include <cuda_runtime.h>
#include <cuda_fp16.h>
#include <cstdint>

#define N_NODES 8192
#define D_FEAT  128
#define C_CLS   10
#define T_TRAIN 1024
#define ND (N_NODES * D_FEAT)

#define INV_SCALE (1.0f / 4096.0f)

// ---------------- scratch (device globals; no allocation allowed) ----------------
__device__ __align__(128) __half g_Sh[N_NODES * 256];    // [s_r|s_i] node-major fp16
__device__ __align__(128) __half g_STh[256 * N_NODES];   // S^T fp16 [256,8192] K-major (GEMM B)
__device__ __align__(128) __half g_Ph[2 * N_NODES * 256];// K-split partial sums (fp16)
__device__ __align__(128) __half g_Msgh[N_NODES * 256];  // combined msg fp16 [8192,256]
__device__ __align__(128) float  g_in[2 * N_NODES];      // in_r, in_i
__device__ __align__(128) float  g_pn[N_NODES * C_CLS];  // pseudo_norm
__device__ __align__(128) __half g_Wbigh[256 * 256];     // [[Wr,-Wi],[Wi,Wr]] K-major fp16

// ---------------- helpers ----------------
__device__ __forceinline__ void cp16(uint32_t smem, const void* g) {
    asm volatile("cp.async.cg.shared.global [%0], [%1], 16;\n" :: "r"(smem), "l"(g));
}
// exact x4096 via exponent add (adj >= 0; 0 stays ~0 after f16 round)
__device__ __forceinline__ uint32_t packh2_scaled(float x, float y) {
    float xs = __uint_as_float(__float_as_uint(x) + 0x06000000u);
    float ys = __uint_as_float(__float_as_uint(y) + 0x06000000u);
    __half2 h = __floats2half2_rn(xs, ys);
    return *reinterpret_cast<uint32_t*>(&h);
}
__device__ __forceinline__ uint32_t packh2(float x, float y) {
    __half2 h = __floats2half2_rn(x, y);
    return *reinterpret_cast<uint32_t*>(&h);
}
#define LDSM_X4(r0, r1, r2, r3, addr) \
    asm volatile("ldmatrix.sync.aligned.m8n8.x4.shared.b16 {%0,%1,%2,%3}, [%4];" \
        : "=r"(r0), "=r"(r1), "=r"(r2), "=r"(r3) : "r"(addr))

// ---------------- K1: per-node prep (+ fused fp16 Wbig build in extra blocks) ----------------
__global__ __launch_bounds__(256) void k_node_prep(
    const float* __restrict__ xr_g, const float* __restrict__ xi_g,
    const float* __restrict__ Wcr, const float* __restrict__ Wci,
    const float* __restrict__ bcr, const float* __restrict__ bci,
    const float* __restrict__ thr, const float* __restrict__ thi,
    const float* __restrict__ Wr_mlp, const float* __restrict__ Wi_mlp)
{
    if (blockIdx.x >= 1024) {
        int idx = (blockIdx.x - 1024) * 256 + threadIdx.x;
        int d = idx >> 8, e = idx & 255;
        float v;
        if (d < 128) v = (e < 128) ? Wr_mlp[d * 128 + e] : -Wi_mlp[d * 128 + (e - 128)];
        else {
            int dd = d - 128;
            v = (e < 128) ? Wi_mlp[dd * 128 + e] : Wr_mlp[dd * 128 + (e - 128)];
        }
        g_Wbigh[idx] = __float2half(v);
        return;
    }

    __shared__ float sWr[C_CLS * 128], sWi[C_CLS * 128];
    __shared__ float sb[4 * C_CLS];
    int tid = threadIdx.x;
    for (int i = tid; i < C_CLS * 128; i += 256) { sWr[i] = Wcr[i]; sWi[i] = Wci[i]; }
    if (tid < C_CLS) {
        sb[tid] = bcr[tid]; sb[C_CLS + tid] = bci[tid];
        sb[2 * C_CLS + tid] = thr[tid]; sb[3 * C_CLS + tid] = thi[tid];
    }
    __syncthreads();

    int wid = tid >> 5, lane = tid & 31;
    int j = blockIdx.x * 8 + wid;

    float xr[4], xi[4];
#pragma unroll
    for (int k = 0; k < 4; k++) {
        xr[k] = xr_g[j * 128 + lane + 32 * k];
        xi[k] = xi_g[j * 128 + lane + 32 * k];
    }

    float pn[C_CLS];
#pragma unroll
    for (int c = 0; c < C_CLS; c++) {
        float p1 = 0.f, p2 = 0.f, p3 = 0.f, p4 = 0.f;
#pragma unroll
        for (int k = 0; k < 4; k++) {
            float wr = sWr[c * 128 + lane + 32 * k];
            float wi = sWi[c * 128 + lane + 32 * k];
            p1 += xr[k] * wr; p2 += xi[k] * wr;
            p3 += xi[k] * wi; p4 += xr[k] * wi;
        }
#pragma unroll
        for (int off = 16; off; off >>= 1) {
            p1 += __shfl_xor_sync(0xffffffffu, p1, off);
            p2 += __shfl_xor_sync(0xffffffffu, p2, off);
            p3 += __shfl_xor_sync(0xffffffffu, p3, off);
            p4 += __shfl_xor_sync(0xffffffffu, p4, off);
        }
        float cr = p1 + sb[c] - p3 - sb[C_CLS + c];
        float ci = p2 + sb[c] + p4 + sb[C_CLS + c];
        pn[c] = sqrtf(cr * cr + ci * ci);
    }

    float m = pn[0];
#pragma unroll
    for (int c = 1; c < C_CLS; c++) m = fmaxf(m, pn[c]);
    float s = 0.f, e[C_CLS];
#pragma unroll
    for (int c = 0; c < C_CLS; c++) { e[c] = expf(pn[c] - m); s += e[c]; }
    float inv = 1.0f / s, inr = 0.f, ini = 0.f;
#pragma unroll
    for (int c = 0; c < C_CLS; c++) {
        float sc = e[c] * inv;
        inr += sc * sb[2 * C_CLS + c];
        ini += sc * sb[3 * C_CLS + c];
    }

    if (lane == 0) {
#pragma unroll
        for (int c = 0; c < C_CLS; c++) g_pn[j * C_CLS + c] = pn[c];
        g_in[j] = inr; g_in[N_NODES + j] = ini;
    }

#pragma unroll
    for (int k = 0; k < 4; k++) {
        int d = lane + 32 * k;
        g_Sh[j * 256 + d]       = __float2half(inr * xr[k] + ini * xi[k]);
        g_Sh[j * 256 + 128 + d] = __float2half(inr * xi[k] - ini * xr[k]);
    }
}

// ---------------- K1b: transpose + fused losses (extra block column) ----------------
__global__ void k_transp(const float* __restrict__ thi,
                         const int* __restrict__ labels,
                         const int* __restrict__ tidx,
                         float* __restrict__ out)
{
    if (blockIdx.x == 256) {
        if (blockIdx.y != 0) return;
        __shared__ float red[256];
        int tid = threadIdx.y * 32 + threadIdx.x;

        if (tid == 0) {
            float st[C_CLS];
            for (int c = 0; c < C_CLS; c++) st[c] = thi[c];
            for (int i = 1; i < C_CLS; i++) {
                float key = st[i]; int k = i - 1;
                while (k >= 0 && st[k] > key) { st[k + 1] = st[k]; k--; }
                st[k + 1] = key;
            }
            float sum = 0.f, mx = 0.f;
            for (int c = 0; c < C_CLS - 1; c++) {
                float d = fabsf(st[c + 1] - st[c]);
                sum += d; if (d > mx) mx = d;
            }
            float difference = sum / (mx + 1e-6f);
            out[(size_t)2 * ND] = 0.1f / (1e-6f + difference);
        }

        float accn = 0.f;
        for (int t = tid; t < T_TRAIN; t += 256) {
            int row = tidx[t];
            int lab = labels[row];
            float l[C_CLS]; float m = -1e30f;
#pragma unroll
            for (int c = 0; c < C_CLS; c++) { l[c] = g_pn[row * C_CLS + c]; m = fmaxf(m, l[c]); }
            float s = 0.f;
#pragma unroll
            for (int c = 0; c < C_CLS; c++) s += expf(l[c] - m);
            float lse = m + logf(s);
            float lp = 0.f;
#pragma unroll
            for (int c = 0; c < C_CLS; c++) if (c == lab) lp = l[c] - lse;
            accn += -lp;
        }
        red[tid] = accn;
        __syncthreads();
        for (int off = 128; off; off >>= 1) {
            if (tid < off) red[tid] += red[tid + off];
            __syncthreads();
        }
        if (tid == 0) out[(size_t)2 * ND + 1] = red[0] / (float)T_TRAIN * 0.1f;
        return;
    }

    __shared__ __half t[32][33];
    int bx = blockIdx.x;
    int by = blockIdx.y;
    int lx = threadIdx.x, ly = threadIdx.y;
#pragma unroll
    for (int i = 0; i < 32; i += 8)
        t[ly + i][lx] = g_Sh[(size_t)(bx * 32 + ly + i) * 256 + by * 32 + lx];
    __syncthreads();
#pragma unroll
    for (int i = 0; i < 32; i += 8)
        g_STh[(size_t)(by * 32 + ly + i) * N_NODES + bx * 32 + lx] = t[lx][ly + i];
}

// ================= GEMM1 (round-10 mainloop): fp16 mma + ldmatrix + frag DB =================
#define BM 128
#define BN 256
#define BK 32
#define NSPLIT 2
#define KSPLIT (N_NODES / NSPLIT)    // 4096
#define NKT (KSPLIT / BK)            // 128
#define ASTR 40                      // halfs per A smem row (80B)
#define BSTR 40                      // halfs per B smem row (80B)
#define ASTAGE (BM * ASTR)
#define BSTAGE (BN * BSTR)
#define SMEM_G1 ((2 * ASTAGE + 4 * BSTAGE) * 2)   // 102400 B

__global__ __launch_bounds__(256, 1) void k_gemm1(const float* __restrict__ adj) {
    extern __shared__ __align__(16) char smraw[];
    __half* Ah = reinterpret_cast<__half*>(smraw);
    __half* Bs = reinterpret_cast<__half*>(smraw + 2 * ASTAGE * 2);

    int tid = threadIdx.x;
    int m0 = blockIdx.x * BM;
    int kb = blockIdx.z * KSPLIT;
    const float*  Ag = adj + (size_t)m0 * N_NODES + kb;
    const __half* Bg = g_STh + kb;

    uint32_t sAh = (uint32_t)__cvta_generic_to_shared(Ah);
    uint32_t sB  = (uint32_t)__cvta_generic_to_shared(Bs);

    int ar = tid >> 1, ac = (tid & 1) * 16;

    float4 pa[4];
    auto ldgA = [&](int kt) {
        const float4* p = reinterpret_cast<const float4*>(
            Ag + (size_t)ar * N_NODES + kt * BK + ac);
#pragma unroll
        for (int i = 0; i < 4; i++) pa[i] = p[i];
    };
    auto stsA = [&](int st) {
        uint32_t d[8];
#pragma unroll
        for (int i = 0; i < 4; i++) {
            d[2 * i]     = packh2_scaled(pa[i].x, pa[i].y);
            d[2 * i + 1] = packh2_scaled(pa[i].z, pa[i].w);
        }
        uint4* dst = reinterpret_cast<uint4*>(Ah + st * ASTAGE + ar * ASTR + ac);
        dst[0] = make_uint4(d[0], d[1], d[2], d[3]);
        dst[1] = make_uint4(d[4], d[5], d[6], d[7]);
    };

    auto loadB = [&](int kt) {
        int st = kt & 3;
        int k0 = kt * BK;
#pragma unroll
        for (int i = 0; i < 4; i++) {
            int v = tid + i * 256;
            int r = v >> 2, c = v & 3;
            cp16(sB + (uint32_t)(st * BSTAGE + r * BSTR + c * 8) * 2,
                 Bg + (size_t)r * N_NODES + k0 + c * 8);
        }
        asm volatile("cp.async.commit_group;\n");
    };

    float acc[4][8][4];
#pragma unroll
    for (int a = 0; a < 4; a++)
#pragma unroll
        for (int b = 0; b < 8; b++)
#pragma unroll
            for (int c = 0; c < 4; c++) acc[a][b][c] = 0.f;

    int wid = tid >> 5, lane = tid & 31;
    int wm = (wid & 1) * 64;
    int wn = (wid >> 1) * 64;

    uint32_t Af[2][16], Bf[2][16];

    int a_row = lane & 15, a_half = (lane >> 4) * 8;
    int b_q = lane >> 3, b_r = lane & 7;
    int b_nfo = (b_q >> 1), b_half = (b_q & 1) * 8;

    auto fragload = [&](int buf, int ast, int bst, int k0) {
#pragma unroll
        for (int mf = 0; mf < 4; mf++) {
            uint32_t ad = sAh + (uint32_t)(ast * ASTAGE +
                (wm + mf * 16 + a_row) * ASTR + k0 + a_half) * 2;
            LDSM_X4(Af[buf][mf * 4 + 0], Af[buf][mf * 4 + 1],
                    Af[buf][mf * 4 + 2], Af[buf][mf * 4 + 3], ad);
        }
#pragma unroll
        for (int p = 0; p < 4; p++) {
            int nf = p * 2 + b_nfo;
            uint32_t ad = sB + (uint32_t)(bst * BSTAGE +
                (wn + nf * 8 + b_r) * BSTR + k0 + b_half) * 2;
            LDSM_X4(Bf[buf][p * 4 + 0], Bf[buf][p * 4 + 1],
                    Bf[buf][p * 4 + 2], Bf[buf][p * 4 + 3], ad);
        }
    };

    auto mma_all = [&](int buf) {
#pragma unroll
        for (int nf = 0; nf < 8; nf++) {
            uint32_t b0 = Bf[buf][(nf >> 1) * 4 + (nf & 1) * 2];
            uint32_t b1 = Bf[buf][(nf >> 1) * 4 + (nf & 1) * 2 + 1];
#pragma unroll
            for (int mf = 0; mf < 4; mf++) {
                asm volatile(
                    "mma.sync.aligned.m16n8k16.row.col.f32.f16.f16.f32 "
                    "{%0,%1,%2,%3}, {%4,%5,%6,%7}, {%8,%9}, {%0,%1,%2,%3};\n"
                    : "+f"(acc[mf][nf][0]), "+f"(acc[mf][nf][1]),
                      "+f"(acc[mf][nf][2]), "+f"(acc[mf][nf][3])
                    : "r"(Af[buf][mf * 4 + 0]), "r"(Af[buf][mf * 4 + 1]),
                      "r"(Af[buf][mf * 4 + 2]), "r"(Af[buf][mf * 4 + 3]),
                      "r"(b0), "r"(b1));
            }
        }
    };

    ldgA(0);
    loadB(0); loadB(1); loadB(2);
    stsA(0);
    ldgA(1);
    asm volatile("cp.async.wait_group 2;\n");
    __syncthreads();

    for (int kt = 0; kt < NKT; kt++) {
        if (kt + 3 < NKT) loadB(kt + 3);
        fragload(0, kt & 1, kt & 3, 0);
        fragload(1, kt & 1, kt & 3, 16);
        mma_all(0);
        if (kt + 1 < NKT) {
            stsA((kt + 1) & 1);
            if (kt + 2 < NKT) ldgA(kt + 2);
        }
        mma_all(1);
        if (kt + 1 < NKT) {
            int rem = NKT - 2 - kt;
            if (rem >= 2)      asm volatile("cp.async.wait_group 2;\n");
            else if (rem == 1) asm volatile("cp.async.wait_group 1;\n");
            else               asm volatile("cp.async.wait_group 0;\n");
            __syncthreads();
        }
    }

    // epilogue: fp16 partial store (half the bytes)
    int g = lane >> 2, tg = lane & 3;
    __half* P = g_Ph + (size_t)blockIdx.z * (N_NODES * 256);
#pragma unroll
    for (int mf = 0; mf < 4; mf++)
#pragma unroll
        for (int nf = 0; nf < 8; nf++) {
            int row = m0 + wm + mf * 16 + g;
            int col = wn + nf * 8 + 2 * tg;
            *reinterpret_cast<uint32_t*>(&P[(size_t)row * 256 + col]) =
                packh2(acc[mf][nf][0], acc[mf][nf][1]);
            *reinterpret_cast<uint32_t*>(&P[(size_t)(row + 8) * 256 + col]) =
                packh2(acc[mf][nf][2], acc[mf][nf][3]);
        }
}

// ---------------- K2b: msg = diag(in)*(P0+P1)/SCALE -> fp16, 8 elems/thread ----------------
__global__ void k_combine2() {
    int t = blockIdx.x * 256 + threadIdx.x;   // 131072 threads
    int n = t >> 4, d0 = (t & 15) * 8;
    size_t b = (size_t)n * 256;
    const size_t PS = (size_t)N_NODES * 256;
    uint4 r0 = *reinterpret_cast<const uint4*>(&g_Ph[b + d0]);
    uint4 r1 = *reinterpret_cast<const uint4*>(&g_Ph[PS + b + d0]);
    uint4 i0 = *reinterpret_cast<const uint4*>(&g_Ph[b + 128 + d0]);
    uint4 i1 = *reinterpret_cast<const uint4*>(&g_Ph[PS + b + 128 + d0]);
    float inr = g_in[n], ini = g_in[N_NODES + n];
    uint4 vr, vi;
#pragma unroll
    for (int q = 0; q < 4; q++) {
        float2 a0 = __half22float2(*reinterpret_cast<__half2*>(&(&r0.x)[q]));
        float2 a1 = __half22float2(*reinterpret_cast<__half2*>(&(&r1.x)[q]));
        float2 c0 = __half22float2(*reinterpret_cast<__half2*>(&(&i0.x)[q]));
        float2 c1 = __half22float2(*reinterpret_cast<__half2*>(&(&i1.x)[q]));
        float mrx = (a0.x + a1.x) * INV_SCALE, mry = (a0.y + a1.y) * INV_SCALE;
        float mix = (c0.x + c1.x) * INV_SCALE, miy = (c0.y + c1.y) * INV_SCALE;
        (&vr.x)[q] = packh2(inr * mrx - ini * mix, inr * mry - ini * miy);
        (&vi.x)[q] = packh2(inr * mix + ini * mrx, inr * miy + ini * mry);
    }
    *reinterpret_cast<uint4*>(&g_Msgh[b + d0])       = vr;
    *reinterpret_cast<uint4*>(&g_Msgh[b + 128 + d0]) = vi;
}

// ---------------- K3: MLP GEMM (fp16 m16n8k16, fused bias+residual+split) ----------------
#define KT2  32
#define MSTR 40   // halfs per smem row (80B)

__global__ __launch_bounds__(256) void k_gemm_mlp(
    const float* __restrict__ br, const float* __restrict__ bi,
    const float* __restrict__ xr, const float* __restrict__ xi,
    float* __restrict__ out)
{
    __shared__ __align__(16) __half As2[2][128 * MSTR];
    __shared__ __align__(16) __half Bs2[2][128 * MSTR];

    const int nk = 256 / KT2;   // 8

    int tid = threadIdx.x;
    int m0 = blockIdx.x * 128;
    int n0 = blockIdx.y * 128;
    const __half* Ag = g_Msgh + (size_t)m0 * 256;
    const __half* Bg = g_Wbigh + (size_t)n0 * 256;

    uint32_t sA = (uint32_t)__cvta_generic_to_shared(&As2[0][0]);
    uint32_t sB = (uint32_t)__cvta_generic_to_shared(&Bs2[0][0]);

    auto load_stage = [&](int buf, int kt) {
        int k0 = kt * KT2;
#pragma unroll
        for (int i = 0; i < 2; i++) {
            int v = tid + i * 256;
            int r = v >> 2, c = v & 3;
            cp16(sA + (uint32_t)(buf * 128 * MSTR + r * MSTR + c * 8) * 2,
                 Ag + (size_t)r * 256 + k0 + c * 8);
            cp16(sB + (uint32_t)(buf * 128 * MSTR + r * MSTR + c * 8) * 2,
                 Bg + (size_t)r * 256 + k0 + c * 8);
        }
        asm volatile("cp.async.commit_group;\n");
    };

    float acc[2][8][4];
#pragma unroll
    for (int a = 0; a < 2; a++)
#pragma unroll
        for (int b = 0; b < 8; b++)
#pragma unroll
            for (int c = 0; c < 4; c++) acc[a][b][c] = 0.f;

    int wid = tid >> 5, lane = tid & 31;
    int wm = (wid & 3) * 32;
    int wn = (wid >> 2) * 64;
    int g = lane >> 2, tg = lane & 3;

    load_stage(0, 0);
    for (int kt = 0; kt < nk; kt++) {
        if (kt + 1 < nk) {
            load_stage((kt + 1) & 1, kt + 1);
            asm volatile("cp.async.wait_group 1;\n");
        } else {
            asm volatile("cp.async.wait_group 0;\n");
        }
        __syncthreads();
        const __half* as = &As2[kt & 1][0];
        const __half* bs = &Bs2[kt & 1][0];
#pragma unroll
        for (int kk = 0; kk < 2; kk++) {
            int k0 = kk * 16;
            uint32_t a[2][4], b[8][2];
#pragma unroll
            for (int mf = 0; mf < 2; mf++) {
                int rb = wm + mf * 16;
                const __half* p0 = as + (rb + g) * MSTR + k0 + 2 * tg;
                const __half* p1 = p0 + 8 * MSTR;
                a[mf][0] = *reinterpret_cast<const uint32_t*>(p0);
                a[mf][1] = *reinterpret_cast<const uint32_t*>(p1);
                a[mf][2] = *reinterpret_cast<const uint32_t*>(p0 + 8);
                a[mf][3] = *reinterpret_cast<const uint32_t*>(p1 + 8);
            }
#pragma unroll
            for (int nf = 0; nf < 8; nf++) {
                int nr = wn + nf * 8 + g;
                b[nf][0] = *reinterpret_cast<const uint32_t*>(bs + nr * MSTR + k0 + 2 * tg);
                b[nf][1] = *reinterpret_cast<const uint32_t*>(bs + nr * MSTR + k0 + 2 * tg + 8);
            }
#pragma unroll
            for (int mf = 0; mf < 2; mf++)
#pragma unroll
                for (int nf = 0; nf < 8; nf++) {
                    asm volatile(
                        "mma.sync.aligned.m16n8k16.row.col.f32.f16.f16.f32 "
                        "{%0,%1,%2,%3}, {%4,%5,%6,%7}, {%8,%9}, {%0,%1,%2,%3};\n"
                        : "+f"(acc[mf][nf][0]), "+f"(acc[mf][nf][1]),
                          "+f"(acc[mf][nf][2]), "+f"(acc[mf][nf][3])
                        : "r"(a[mf][0]), "r"(a[mf][1]), "r"(a[mf][2]), "r"(a[mf][3]),
                          "r"(b[nf][0]), "r"(b[nf][1]));
                }
        }
        __syncthreads();
    }

#pragma unroll
    for (int mf = 0; mf < 2; mf++)
#pragma unroll
        for (int nf = 0; nf < 8; nf++) {
            int row = m0 + wm + mf * 16 + g;
            int col = n0 + wn + nf * 8 + 2 * tg;
#pragma unroll
            for (int q = 0; q < 4; q++) {
                int r = row + (q >> 1) * 8;
                int c = col + (q & 1);
                float v = acc[mf][nf][q];
                if (c < 128) {
                    out[(size_t)r * 128 + c] =
                        v + br[c] - bi[c] + xr[(size_t)r * 128 + c];
                } else {
                    int cc = c - 128;
                    out[(size_t)ND + (size_t)r * 128 + cc] =
                        v + br[cc] + bi[cc] + xi[(size_t)r * 128 + cc];
                }
            }
        }
}

// ---------------- launch ----------------
extern "C" void kernel_launch(void* const* d_in, const int* in_sizes, int n_in,
                              void* d_out, int out_size)
{
    const float* x_real     = (const float*)d_in[0];
    const float* x_imag     = (const float*)d_in[1];
    const float* adj        = (const float*)d_in[2];
    const float* theta_real = (const float*)d_in[3];
    const float* theta_imag = (const float*)d_in[4];
    const float* W_r        = (const float*)d_in[5];
    const float* b_r        = (const float*)d_in[6];
    const float* W_i        = (const float*)d_in[7];
    const float* b_i        = (const float*)d_in[8];
    const float* Wc_r       = (const float*)d_in[9];
    const float* bc_r       = (const float*)d_in[10];
    const float* Wc_i       = (const float*)d_in[11];
    const float* bc_i       = (const float*)d_in[12];
    const int*   labels     = (const int*)d_in[13];
    const int*   train_idx  = (const int*)d_in[14];
    float* out = (float*)d_out;

    cudaFuncSetAttribute(k_gemm1, cudaFuncAttributeMaxDynamicSharedMemorySize, SMEM_G1);

    k_node_prep<<<1280, 256>>>(x_real, x_imag, Wc_r, Wc_i, bc_r, bc_i,
                               theta_real, theta_imag, W_r, W_i);
    k_transp<<<dim3(257, 8), dim3(32, 8)>>>(theta_imag, labels, train_idx, out);
    k_gemm1<<<dim3(64, 1, NSPLIT), 256, SMEM_G1>>>(adj);
    k_combine2<<<512, 256>>>();
    k_gemm_mlp<<<dim3(64, 2), 256>>>(b_r, b_i, x_real, x_imag, out);
}

// round 15
// speedup vs baseline: 1.2960x; 1.0037x over previous
#include <cuda_runtime.h>
#include <cuda_fp16.h>
#include <cstdint>

#define N_NODES 8192
#define D_FEAT  128
#define C_CLS   10
#define T_TRAIN 1024
#define ND (N_NODES * D_FEAT)

#define INV_SCALE (1.0f / 4096.0f)

// ---------------- scratch (device globals; no allocation allowed) ----------------
__device__ __align__(128) __half g_STh[256 * N_NODES];   // S^T fp16 [256,8192] K-major (GEMM B)
__device__ __align__(128) __half g_Ph[2 * N_NODES * 256];// K-split partial sums (fp16)
__device__ __align__(128) __half g_Msgh[N_NODES * 256];  // combined msg fp16 [8192,256]
__device__ __align__(128) float  g_in[2 * N_NODES];      // in_r, in_i
__device__ __align__(128) float  g_pn[N_NODES * C_CLS];  // pseudo_norm
__device__ __align__(128) __half g_Wbigh[256 * 256];     // [[Wr,-Wi],[Wi,Wr]] K-major fp16

// ---------------- helpers ----------------
__device__ __forceinline__ void cp16(uint32_t smem, const void* g) {
    asm volatile("cp.async.cg.shared.global [%0], [%1], 16;\n" :: "r"(smem), "l"(g));
}
// exact x4096 via exponent add (adj >= 0; 0 stays ~0 after f16 round)
__device__ __forceinline__ uint32_t packh2_scaled(float x, float y) {
    float xs = __uint_as_float(__float_as_uint(x) + 0x06000000u);
    float ys = __uint_as_float(__float_as_uint(y) + 0x06000000u);
    __half2 h = __floats2half2_rn(xs, ys);
    return *reinterpret_cast<uint32_t*>(&h);
}
__device__ __forceinline__ uint32_t packh2(float x, float y) {
    __half2 h = __floats2half2_rn(x, y);
    return *reinterpret_cast<uint32_t*>(&h);
}
#define LDSM_X4(r0, r1, r2, r3, addr) \
    asm volatile("ldmatrix.sync.aligned.m8n8.x4.shared.b16 {%0,%1,%2,%3}, [%4];" \
        : "=r"(r0), "=r"(r1), "=r"(r2), "=r"(r3) : "r"(addr))

// ---------------- K1: per-node prep + fused transpose (+ fp16 Wbig build blocks) ----------------
// 1024 threads = 32 warps = 32 nodes/block; 256 prep blocks + 64 Wbig blocks.
#define TSTR 34   // halfs per sT row (68B, 17-coprime padding -> conflict-free)

__global__ __launch_bounds__(1024) void k_node_prep(
    const float* __restrict__ xr_g, const float* __restrict__ xi_g,
    const float* __restrict__ Wcr, const float* __restrict__ Wci,
    const float* __restrict__ bcr, const float* __restrict__ bci,
    const float* __restrict__ thr, const float* __restrict__ thi,
    const float* __restrict__ Wr_mlp, const float* __restrict__ Wi_mlp)
{
    if (blockIdx.x >= 256) {
        int idx = (blockIdx.x - 256) * 1024 + threadIdx.x;   // 64 blocks x 1024 = 65536
        int d = idx >> 8, e = idx & 255;
        float v;
        if (d < 128) v = (e < 128) ? Wr_mlp[d * 128 + e] : -Wi_mlp[d * 128 + (e - 128)];
        else {
            int dd = d - 128;
            v = (e < 128) ? Wi_mlp[dd * 128 + e] : Wr_mlp[dd * 128 + (e - 128)];
        }
        g_Wbigh[idx] = __float2half(v);
        return;
    }

    __shared__ float sWr[C_CLS * 128], sWi[C_CLS * 128];
    __shared__ float sb[4 * C_CLS];
    __shared__ __half sT[256 * TSTR];    // transposed s staging: [feat][node]
    int tid = threadIdx.x;
    for (int i = tid; i < C_CLS * 128; i += 1024) { sWr[i] = Wcr[i]; sWi[i] = Wci[i]; }
    if (tid < C_CLS) {
        sb[tid] = bcr[tid]; sb[C_CLS + tid] = bci[tid];
        sb[2 * C_CLS + tid] = thr[tid]; sb[3 * C_CLS + tid] = thi[tid];
    }
    __syncthreads();

    int wid = tid >> 5, lane = tid & 31;
    int j = blockIdx.x * 32 + wid;

    float xr[4], xi[4];
#pragma unroll
    for (int k = 0; k < 4; k++) {
        xr[k] = xr_g[j * 128 + lane + 32 * k];
        xi[k] = xi_g[j * 128 + lane + 32 * k];
    }

    float pn[C_CLS];
#pragma unroll
    for (int c = 0; c < C_CLS; c++) {
        float p1 = 0.f, p2 = 0.f, p3 = 0.f, p4 = 0.f;
#pragma unroll
        for (int k = 0; k < 4; k++) {
            float wr = sWr[c * 128 + lane + 32 * k];
            float wi = sWi[c * 128 + lane + 32 * k];
            p1 += xr[k] * wr; p2 += xi[k] * wr;
            p3 += xi[k] * wi; p4 += xr[k] * wi;
        }
#pragma unroll
        for (int off = 16; off; off >>= 1) {
            p1 += __shfl_xor_sync(0xffffffffu, p1, off);
            p2 += __shfl_xor_sync(0xffffffffu, p2, off);
            p3 += __shfl_xor_sync(0xffffffffu, p3, off);
            p4 += __shfl_xor_sync(0xffffffffu, p4, off);
        }
        float cr = p1 + sb[c] - p3 - sb[C_CLS + c];
        float ci = p2 + sb[c] + p4 + sb[C_CLS + c];
        pn[c] = sqrtf(cr * cr + ci * ci);
    }

    float m = pn[0];
#pragma unroll
    for (int c = 1; c < C_CLS; c++) m = fmaxf(m, pn[c]);
    float s = 0.f, e[C_CLS];
#pragma unroll
    for (int c = 0; c < C_CLS; c++) { e[c] = expf(pn[c] - m); s += e[c]; }
    float inv = 1.0f / s, inr = 0.f, ini = 0.f;
#pragma unroll
    for (int c = 0; c < C_CLS; c++) {
        float sc = e[c] * inv;
        inr += sc * sb[2 * C_CLS + c];
        ini += sc * sb[3 * C_CLS + c];
    }

    if (lane == 0) {
#pragma unroll
        for (int c = 0; c < C_CLS; c++) g_pn[j * C_CLS + c] = pn[c];
        g_in[j] = inr; g_in[N_NODES + j] = ini;
    }

    // stage s into transposed smem tile
#pragma unroll
    for (int k = 0; k < 4; k++) {
        int d = lane + 32 * k;
        sT[d * TSTR + wid]         = __float2half(inr * xr[k] + ini * xi[k]);
        sT[(128 + d) * TSTR + wid] = __float2half(inr * xi[k] - ini * xr[k]);
    }
    __syncthreads();

    // coalesced write-out: thread t -> feat row r = t>>2, 8 halfs at (t&3)*8
    {
        int r = tid >> 2, q = tid & 3;
        const __half* src = &sT[r * TSTR + q * 8];
        uint32_t w0 = *reinterpret_cast<const uint32_t*>(src);       // 4B-aligned reads
        uint32_t w1 = *reinterpret_cast<const uint32_t*>(src + 2);
        uint32_t w2 = *reinterpret_cast<const uint32_t*>(src + 4);
        uint32_t w3 = *reinterpret_cast<const uint32_t*>(src + 6);
        *reinterpret_cast<uint4*>(&g_STh[(size_t)r * N_NODES + blockIdx.x * 32 + q * 8]) =
            make_uint4(w0, w1, w2, w3);
    }
}

// ================= GEMM1 (round-10 mainloop, frozen): fp16 mma + ldmatrix + frag DB =================
#define BM 128
#define BN 256
#define BK 32
#define NSPLIT 2
#define KSPLIT (N_NODES / NSPLIT)    // 4096
#define NKT (KSPLIT / BK)            // 128
#define ASTR 40                      // halfs per A smem row (80B)
#define BSTR 40                      // halfs per B smem row (80B)
#define ASTAGE (BM * ASTR)
#define BSTAGE (BN * BSTR)
#define SMEM_G1 ((2 * ASTAGE + 4 * BSTAGE) * 2)   // 102400 B

__global__ __launch_bounds__(256, 1) void k_gemm1(const float* __restrict__ adj) {
    extern __shared__ __align__(16) char smraw[];
    __half* Ah = reinterpret_cast<__half*>(smraw);
    __half* Bs = reinterpret_cast<__half*>(smraw + 2 * ASTAGE * 2);

    int tid = threadIdx.x;
    int m0 = blockIdx.x * BM;
    int kb = blockIdx.z * KSPLIT;
    const float*  Ag = adj + (size_t)m0 * N_NODES + kb;
    const __half* Bg = g_STh + kb;

    uint32_t sAh = (uint32_t)__cvta_generic_to_shared(Ah);
    uint32_t sB  = (uint32_t)__cvta_generic_to_shared(Bs);

    int ar = tid >> 1, ac = (tid & 1) * 16;

    float4 pa[4];
    auto ldgA = [&](int kt) {
        const float4* p = reinterpret_cast<const float4*>(
            Ag + (size_t)ar * N_NODES + kt * BK + ac);
#pragma unroll
        for (int i = 0; i < 4; i++) pa[i] = p[i];
    };
    auto stsA = [&](int st) {
        uint32_t d[8];
#pragma unroll
        for (int i = 0; i < 4; i++) {
            d[2 * i]     = packh2_scaled(pa[i].x, pa[i].y);
            d[2 * i + 1] = packh2_scaled(pa[i].z, pa[i].w);
        }
        uint4* dst = reinterpret_cast<uint4*>(Ah + st * ASTAGE + ar * ASTR + ac);
        dst[0] = make_uint4(d[0], d[1], d[2], d[3]);
        dst[1] = make_uint4(d[4], d[5], d[6], d[7]);
    };

    auto loadB = [&](int kt) {
        int st = kt & 3;
        int k0 = kt * BK;
#pragma unroll
        for (int i = 0; i < 4; i++) {
            int v = tid + i * 256;
            int r = v >> 2, c = v & 3;
            cp16(sB + (uint32_t)(st * BSTAGE + r * BSTR + c * 8) * 2,
                 Bg + (size_t)r * N_NODES + k0 + c * 8);
        }
        asm volatile("cp.async.commit_group;\n");
    };

    float acc[4][8][4];
#pragma unroll
    for (int a = 0; a < 4; a++)
#pragma unroll
        for (int b = 0; b < 8; b++)
#pragma unroll
            for (int c = 0; c < 4; c++) acc[a][b][c] = 0.f;

    int wid = tid >> 5, lane = tid & 31;
    int wm = (wid & 1) * 64;
    int wn = (wid >> 1) * 64;

    uint32_t Af[2][16], Bf[2][16];

    int a_row = lane & 15, a_half = (lane >> 4) * 8;
    int b_q = lane >> 3, b_r = lane & 7;
    int b_nfo = (b_q >> 1), b_half = (b_q & 1) * 8;

    auto fragload = [&](int buf, int ast, int bst, int k0) {
#pragma unroll
        for (int mf = 0; mf < 4; mf++) {
            uint32_t ad = sAh + (uint32_t)(ast * ASTAGE +
                (wm + mf * 16 + a_row) * ASTR + k0 + a_half) * 2;
            LDSM_X4(Af[buf][mf * 4 + 0], Af[buf][mf * 4 + 1],
                    Af[buf][mf * 4 + 2], Af[buf][mf * 4 + 3], ad);
        }
#pragma unroll
        for (int p = 0; p < 4; p++) {
            int nf = p * 2 + b_nfo;
            uint32_t ad = sB + (uint32_t)(bst * BSTAGE +
                (wn + nf * 8 + b_r) * BSTR + k0 + b_half) * 2;
            LDSM_X4(Bf[buf][p * 4 + 0], Bf[buf][p * 4 + 1],
                    Bf[buf][p * 4 + 2], Bf[buf][p * 4 + 3], ad);
        }
    };

    auto mma_all = [&](int buf) {
#pragma unroll
        for (int nf = 0; nf < 8; nf++) {
            uint32_t b0 = Bf[buf][(nf >> 1) * 4 + (nf & 1) * 2];
            uint32_t b1 = Bf[buf][(nf >> 1) * 4 + (nf & 1) * 2 + 1];
#pragma unroll
            for (int mf = 0; mf < 4; mf++) {
                asm volatile(
                    "mma.sync.aligned.m16n8k16.row.col.f32.f16.f16.f32 "
                    "{%0,%1,%2,%3}, {%4,%5,%6,%7}, {%8,%9}, {%0,%1,%2,%3};\n"
                    : "+f"(acc[mf][nf][0]), "+f"(acc[mf][nf][1]),
                      "+f"(acc[mf][nf][2]), "+f"(acc[mf][nf][3])
                    : "r"(Af[buf][mf * 4 + 0]), "r"(Af[buf][mf * 4 + 1]),
                      "r"(Af[buf][mf * 4 + 2]), "r"(Af[buf][mf * 4 + 3]),
                      "r"(b0), "r"(b1));
            }
        }
    };

    ldgA(0);
    loadB(0); loadB(1); loadB(2);
    stsA(0);
    ldgA(1);
    asm volatile("cp.async.wait_group 2;\n");
    __syncthreads();

    for (int kt = 0; kt < NKT; kt++) {
        if (kt + 3 < NKT) loadB(kt + 3);
        fragload(0, kt & 1, kt & 3, 0);
        fragload(1, kt & 1, kt & 3, 16);
        mma_all(0);
        if (kt + 1 < NKT) {
            stsA((kt + 1) & 1);
            if (kt + 2 < NKT) ldgA(kt + 2);
        }
        mma_all(1);
        if (kt + 1 < NKT) {
            int rem = NKT - 2 - kt;
            if (rem >= 2)      asm volatile("cp.async.wait_group 2;\n");
            else if (rem == 1) asm volatile("cp.async.wait_group 1;\n");
            else               asm volatile("cp.async.wait_group 0;\n");
            __syncthreads();
        }
    }

    // epilogue: fp16 partial store
    int g = lane >> 2, tg = lane & 3;
    __half* P = g_Ph + (size_t)blockIdx.z * (N_NODES * 256);
#pragma unroll
    for (int mf = 0; mf < 4; mf++)
#pragma unroll
        for (int nf = 0; nf < 8; nf++) {
            int row = m0 + wm + mf * 16 + g;
            int col = wn + nf * 8 + 2 * tg;
            *reinterpret_cast<uint32_t*>(&P[(size_t)row * 256 + col]) =
                packh2(acc[mf][nf][0], acc[mf][nf][1]);
            *reinterpret_cast<uint32_t*>(&P[(size_t)(row + 8) * 256 + col]) =
                packh2(acc[mf][nf][2], acc[mf][nf][3]);
        }
}

// ---------------- K2b: combine (8 elems/thread) + fused losses block ----------------
__global__ void k_combine2(const float* __restrict__ thi,
                           const int* __restrict__ labels,
                           const int* __restrict__ tidx,
                           float* __restrict__ out)
{
    if (blockIdx.x == 512) {
        __shared__ float red[256];
        int tid = threadIdx.x;

        if (tid == 0) {
            float st[C_CLS];
            for (int c = 0; c < C_CLS; c++) st[c] = thi[c];
            for (int i = 1; i < C_CLS; i++) {
                float key = st[i]; int k = i - 1;
                while (k >= 0 && st[k] > key) { st[k + 1] = st[k]; k--; }
                st[k + 1] = key;
            }
            float sum = 0.f, mx = 0.f;
            for (int c = 0; c < C_CLS - 1; c++) {
                float d = fabsf(st[c + 1] - st[c]);
                sum += d; if (d > mx) mx = d;
            }
            float difference = sum / (mx + 1e-6f);
            out[(size_t)2 * ND] = 0.1f / (1e-6f + difference);
        }

        float accn = 0.f;
        for (int t = tid; t < T_TRAIN; t += 256) {
            int row = tidx[t];
            int lab = labels[row];
            float l[C_CLS]; float m = -1e30f;
#pragma unroll
            for (int c = 0; c < C_CLS; c++) { l[c] = g_pn[row * C_CLS + c]; m = fmaxf(m, l[c]); }
            float s = 0.f;
#pragma unroll
            for (int c = 0; c < C_CLS; c++) s += expf(l[c] - m);
            float lse = m + logf(s);
            float lp = 0.f;
#pragma unroll
            for (int c = 0; c < C_CLS; c++) if (c == lab) lp = l[c] - lse;
            accn += -lp;
        }
        red[tid] = accn;
        __syncthreads();
        for (int off = 128; off; off >>= 1) {
            if (tid < off) red[tid] += red[tid + off];
            __syncthreads();
        }
        if (tid == 0) out[(size_t)2 * ND + 1] = red[0] / (float)T_TRAIN * 0.1f;
        return;
    }

    int t = blockIdx.x * 256 + threadIdx.x;   // 131072 threads
    int n = t >> 4, d0 = (t & 15) * 8;
    size_t b = (size_t)n * 256;
    const size_t PS = (size_t)N_NODES * 256;
    uint4 r0 = *reinterpret_cast<const uint4*>(&g_Ph[b + d0]);
    uint4 r1 = *reinterpret_cast<const uint4*>(&g_Ph[PS + b + d0]);
    uint4 i0 = *reinterpret_cast<const uint4*>(&g_Ph[b + 128 + d0]);
    uint4 i1 = *reinterpret_cast<const uint4*>(&g_Ph[PS + b + 128 + d0]);
    float inr = g_in[n], ini = g_in[N_NODES + n];
    uint4 vr, vi;
#pragma unroll
    for (int q = 0; q < 4; q++) {
        float2 a0 = __half22float2(*reinterpret_cast<__half2*>(&(&r0.x)[q]));
        float2 a1 = __half22float2(*reinterpret_cast<__half2*>(&(&r1.x)[q]));
        float2 c0 = __half22float2(*reinterpret_cast<__half2*>(&(&i0.x)[q]));
        float2 c1 = __half22float2(*reinterpret_cast<__half2*>(&(&i1.x)[q]));
        float mrx = (a0.x + a1.x) * INV_SCALE, mry = (a0.y + a1.y) * INV_SCALE;
        float mix = (c0.x + c1.x) * INV_SCALE, miy = (c0.y + c1.y) * INV_SCALE;
        (&vr.x)[q] = packh2(inr * mrx - ini * mix, inr * mry - ini * miy);
        (&vi.x)[q] = packh2(inr * mix + ini * mrx, inr * miy + ini * mry);
    }
    *reinterpret_cast<uint4*>(&g_Msgh[b + d0])       = vr;
    *reinterpret_cast<uint4*>(&g_Msgh[b + 128 + d0]) = vi;
}

// ---------------- K3: MLP GEMM (fp16 m16n8k16, fused bias+residual+split) ----------------
#define KT2  32
#define MSTR 40   // halfs per smem row (80B)

__global__ __launch_bounds__(256) void k_gemm_mlp(
    const float* __restrict__ br, const float* __restrict__ bi,
    const float* __restrict__ xr, const float* __restrict__ xi,
    float* __restrict__ out)
{
    __shared__ __align__(16) __half As2[2][128 * MSTR];
    __shared__ __align__(16) __half Bs2[2][128 * MSTR];

    const int nk = 256 / KT2;   // 8

    int tid = threadIdx.x;
    int m0 = blockIdx.x * 128;
    int n0 = blockIdx.y * 128;
    const __half* Ag = g_Msgh + (size_t)m0 * 256;
    const __half* Bg = g_Wbigh + (size_t)n0 * 256;

    uint32_t sA = (uint32_t)__cvta_generic_to_shared(&As2[0][0]);
    uint32_t sB = (uint32_t)__cvta_generic_to_shared(&Bs2[0][0]);

    auto load_stage = [&](int buf, int kt) {
        int k0 = kt * KT2;
#pragma unroll
        for (int i = 0; i < 2; i++) {
            int v = tid + i * 256;
            int r = v >> 2, c = v & 3;
            cp16(sA + (uint32_t)(buf * 128 * MSTR + r * MSTR + c * 8) * 2,
                 Ag + (size_t)r * 256 + k0 + c * 8);
            cp16(sB + (uint32_t)(buf * 128 * MSTR + r * MSTR + c * 8) * 2,
                 Bg + (size_t)r * 256 + k0 + c * 8);
        }
        asm volatile("cp.async.commit_group;\n");
    };

    float acc[2][8][4];
#pragma unroll
    for (int a = 0; a < 2; a++)
#pragma unroll
        for (int b = 0; b < 8; b++)
#pragma unroll
            for (int c = 0; c < 4; c++) acc[a][b][c] = 0.f;

    int wid = tid >> 5, lane = tid & 31;
    int wm = (wid & 3) * 32;
    int wn = (wid >> 2) * 64;
    int g = lane >> 2, tg = lane & 3;

    load_stage(0, 0);
    for (int kt = 0; kt < nk; kt++) {
        if (kt + 1 < nk) {
            load_stage((kt + 1) & 1, kt + 1);
            asm volatile("cp.async.wait_group 1;\n");
        } else {
            asm volatile("cp.async.wait_group 0;\n");
        }
        __syncthreads();
        const __half* as = &As2[kt & 1][0];
        const __half* bs = &Bs2[kt & 1][0];
#pragma unroll
        for (int kk = 0; kk < 2; kk++) {
            int k0 = kk * 16;
            uint32_t a[2][4], b[8][2];
#pragma unroll
            for (int mf = 0; mf < 2; mf++) {
                int rb = wm + mf * 16;
                const __half* p0 = as + (rb + g) * MSTR + k0 + 2 * tg;
                const __half* p1 = p0 + 8 * MSTR;
                a[mf][0] = *reinterpret_cast<const uint32_t*>(p0);
                a[mf][1] = *reinterpret_cast<const uint32_t*>(p1);
                a[mf][2] = *reinterpret_cast<const uint32_t*>(p0 + 8);
                a[mf][3] = *reinterpret_cast<const uint32_t*>(p1 + 8);
            }
#pragma unroll
            for (int nf = 0; nf < 8; nf++) {
                int nr = wn + nf * 8 + g;
                b[nf][0] = *reinterpret_cast<const uint32_t*>(bs + nr * MSTR + k0 + 2 * tg);
                b[nf][1] = *reinterpret_cast<const uint32_t*>(bs + nr * MSTR + k0 + 2 * tg + 8);
            }
#pragma unroll
            for (int mf = 0; mf < 2; mf++)
#pragma unroll
                for (int nf = 0; nf < 8; nf++) {
                    asm volatile(
                        "mma.sync.aligned.m16n8k16.row.col.f32.f16.f16.f32 "
                        "{%0,%1,%2,%3}, {%4,%5,%6,%7}, {%8,%9}, {%0,%1,%2,%3};\n"
                        : "+f"(acc[mf][nf][0]), "+f"(acc[mf][nf][1]),
                          "+f"(acc[mf][nf][2]), "+f"(acc[mf][nf][3])
                        : "r"(a[mf][0]), "r"(a[mf][1]), "r"(a[mf][2]), "r"(a[mf][3]),
                          "r"(b[nf][0]), "r"(b[nf][1]));
                }
        }
        __syncthreads();
    }

#pragma unroll
    for (int mf = 0; mf < 2; mf++)
#pragma unroll
        for (int nf = 0; nf < 8; nf++) {
            int row = m0 + wm + mf * 16 + g;
            int col = n0 + wn + nf * 8 + 2 * tg;
#pragma unroll
            for (int q = 0; q < 4; q++) {
                int r = row + (q >> 1) * 8;
                int c = col + (q & 1);
                float v = acc[mf][nf][q];
                if (c < 128) {
                    out[(size_t)r * 128 + c] =
                        v + br[c] - bi[c] + xr[(size_t)r * 128 + c];
                } else {
                    int cc = c - 128;
                    out[(size_t)ND + (size_t)r * 128 + cc] =
                        v + br[cc] + bi[cc] + xi[(size_t)r * 128 + cc];
                }
            }
        }
}

// ---------------- launch ----------------
extern "C" void kernel_launch(void* const* d_in, const int* in_sizes, int n_in,
                              void* d_out, int out_size)
{
    const float* x_real     = (const float*)d_in[0];
    const float* x_imag     = (const float*)d_in[1];
    const float* adj        = (const float*)d_in[2];
    const float* theta_real = (const float*)d_in[3];
    const float* theta_imag = (const float*)d_in[4];
    const float* W_r        = (const float*)d_in[5];
    const float* b_r        = (const float*)d_in[6];
    const float* W_i        = (const float*)d_in[7];
    const float* b_i        = (const float*)d_in[8];
    const float* Wc_r       = (const float*)d_in[9];
    const float* bc_r       = (const float*)d_in[10];
    const float* Wc_i       = (const float*)d_in[11];
    const float* bc_i       = (const float*)d_in[12];
    const int*   labels     = (const int*)d_in[13];
    const int*   train_idx  = (const int*)d_in[14];
    float* out = (float*)d_out;

    cudaFuncSetAttribute(k_gemm1, cudaFuncAttributeMaxDynamicSharedMemorySize, SMEM_G1);

    k_node_prep<<<320, 1024>>>(x_real, x_imag, Wc_r, Wc_i, bc_r, bc_i,
                               theta_real, theta_imag, W_r, W_i);
    k_gemm1<<<dim3(64, 1, NSPLIT), 256, SMEM_G1>>>(adj);
    k_combine2<<<513, 256>>>(theta_imag, labels, train_idx, out);
    k_gemm_mlp<<<dim3(64, 2), 256>>>(b_r, b_i, x_real, x_imag, out);
}

// round 16
// speedup vs baseline: 1.3779x; 1.0632x over previous
#include <cuda_runtime.h>
#include <cuda_fp16.h>
#include <cstdint>

#define N_NODES 8192
#define D_FEAT  128
#define C_CLS   10
#define T_TRAIN 1024
#define ND (N_NODES * D_FEAT)

#define INV_SCALE (1.0f / 4096.0f)

// ---------------- scratch (device globals; no allocation allowed) ----------------
__device__ __align__(128) __half g_STh[256 * N_NODES];   // S^T fp16 [256,8192] K-major (GEMM B)
__device__ __align__(128) __half g_Ph[2 * N_NODES * 256];// K-split partial sums (fp16)
__device__ __align__(128) __half g_Msgh[N_NODES * 256];  // combined msg fp16 [8192,256]
__device__ __align__(128) float  g_in[2 * N_NODES];      // in_r, in_i
__device__ __align__(128) float  g_pn[N_NODES * C_CLS];  // pseudo_norm
__device__ __align__(128) __half g_Wbigh[256 * 256];     // [[Wr,-Wi],[Wi,Wr]] K-major fp16

// ---------------- helpers ----------------
__device__ __forceinline__ void cp16(uint32_t smem, const void* g) {
    asm volatile("cp.async.cg.shared.global [%0], [%1], 16;\n" :: "r"(smem), "l"(g));
}
// exact x4096 via exponent add (adj >= 0; 0 stays ~0 after f16 round)
__device__ __forceinline__ uint32_t packh2_scaled(float x, float y) {
    float xs = __uint_as_float(__float_as_uint(x) + 0x06000000u);
    float ys = __uint_as_float(__float_as_uint(y) + 0x06000000u);
    __half2 h = __floats2half2_rn(xs, ys);
    return *reinterpret_cast<uint32_t*>(&h);
}
__device__ __forceinline__ uint32_t packh2(float x, float y) {
    __half2 h = __floats2half2_rn(x, y);
    return *reinterpret_cast<uint32_t*>(&h);
}
#define LDSM_X4(r0, r1, r2, r3, addr) \
    asm volatile("ldmatrix.sync.aligned.m8n8.x4.shared.b16 {%0,%1,%2,%3}, [%4];" \
        : "=r"(r0), "=r"(r1), "=r"(r2), "=r"(r3) : "r"(addr))

// ---------------- K1: per-node prep + fused transpose (+ fp16 Wbig build blocks) ----------------
#define TSTR 34   // halfs per sT row (68B, conflict-free)

__global__ __launch_bounds__(1024) void k_node_prep(
    const float* __restrict__ xr_g, const float* __restrict__ xi_g,
    const float* __restrict__ Wcr, const float* __restrict__ Wci,
    const float* __restrict__ bcr, const float* __restrict__ bci,
    const float* __restrict__ thr, const float* __restrict__ thi,
    const float* __restrict__ Wr_mlp, const float* __restrict__ Wi_mlp)
{
    if (blockIdx.x >= 256) {
        int idx = (blockIdx.x - 256) * 1024 + threadIdx.x;   // 64 blocks x 1024 = 65536
        int d = idx >> 8, e = idx & 255;
        float v;
        if (d < 128) v = (e < 128) ? Wr_mlp[d * 128 + e] : -Wi_mlp[d * 128 + (e - 128)];
        else {
            int dd = d - 128;
            v = (e < 128) ? Wi_mlp[dd * 128 + e] : Wr_mlp[dd * 128 + (e - 128)];
        }
        g_Wbigh[idx] = __float2half(v);
        return;
    }

    __shared__ float sWr[C_CLS * 128], sWi[C_CLS * 128];
    __shared__ float sb[4 * C_CLS];
    __shared__ __half sT[256 * TSTR];
    int tid = threadIdx.x;
    for (int i = tid; i < C_CLS * 128; i += 1024) { sWr[i] = Wcr[i]; sWi[i] = Wci[i]; }
    if (tid < C_CLS) {
        sb[tid] = bcr[tid]; sb[C_CLS + tid] = bci[tid];
        sb[2 * C_CLS + tid] = thr[tid]; sb[3 * C_CLS + tid] = thi[tid];
    }
    __syncthreads();

    int wid = tid >> 5, lane = tid & 31;
    int j = blockIdx.x * 32 + wid;

    float xr[4], xi[4];
#pragma unroll
    for (int k = 0; k < 4; k++) {
        xr[k] = xr_g[j * 128 + lane + 32 * k];
        xi[k] = xi_g[j * 128 + lane + 32 * k];
    }

    float pn[C_CLS];
#pragma unroll
    for (int c = 0; c < C_CLS; c++) {
        float p1 = 0.f, p2 = 0.f, p3 = 0.f, p4 = 0.f;
#pragma unroll
        for (int k = 0; k < 4; k++) {
            float wr = sWr[c * 128 + lane + 32 * k];
            float wi = sWi[c * 128 + lane + 32 * k];
            p1 += xr[k] * wr; p2 += xi[k] * wr;
            p3 += xi[k] * wi; p4 += xr[k] * wi;
        }
#pragma unroll
        for (int off = 16; off; off >>= 1) {
            p1 += __shfl_xor_sync(0xffffffffu, p1, off);
            p2 += __shfl_xor_sync(0xffffffffu, p2, off);
            p3 += __shfl_xor_sync(0xffffffffu, p3, off);
            p4 += __shfl_xor_sync(0xffffffffu, p4, off);
        }
        float cr = p1 + sb[c] - p3 - sb[C_CLS + c];
        float ci = p2 + sb[c] + p4 + sb[C_CLS + c];
        pn[c] = sqrtf(cr * cr + ci * ci);
    }

    float m = pn[0];
#pragma unroll
    for (int c = 1; c < C_CLS; c++) m = fmaxf(m, pn[c]);
    float s = 0.f, e[C_CLS];
#pragma unroll
    for (int c = 0; c < C_CLS; c++) { e[c] = expf(pn[c] - m); s += e[c]; }
    float inv = 1.0f / s, inr = 0.f, ini = 0.f;
#pragma unroll
    for (int c = 0; c < C_CLS; c++) {
        float sc = e[c] * inv;
        inr += sc * sb[2 * C_CLS + c];
        ini += sc * sb[3 * C_CLS + c];
    }

    if (lane == 0) {
#pragma unroll
        for (int c = 0; c < C_CLS; c++) g_pn[j * C_CLS + c] = pn[c];
        g_in[j] = inr; g_in[N_NODES + j] = ini;
    }

#pragma unroll
    for (int k = 0; k < 4; k++) {
        int d = lane + 32 * k;
        sT[d * TSTR + wid]         = __float2half(inr * xr[k] + ini * xi[k]);
        sT[(128 + d) * TSTR + wid] = __float2half(inr * xi[k] - ini * xr[k]);
    }
    __syncthreads();

    {
        int r = tid >> 2, q = tid & 3;
        const __half* src = &sT[r * TSTR + q * 8];
        uint32_t w0 = *reinterpret_cast<const uint32_t*>(src);
        uint32_t w1 = *reinterpret_cast<const uint32_t*>(src + 2);
        uint32_t w2 = *reinterpret_cast<const uint32_t*>(src + 4);
        uint32_t w3 = *reinterpret_cast<const uint32_t*>(src + 6);
        *reinterpret_cast<uint4*>(&g_STh[(size_t)r * N_NODES + blockIdx.x * 32 + q * 8]) =
            make_uint4(w0, w1, w2, w3);
    }
}

// ================= GEMM1 (frozen round-10 mainloop): fp16 mma + ldmatrix + frag DB =================
#define BM 128
#define BN 256
#define BK 32
#define NSPLIT 2
#define KSPLIT (N_NODES / NSPLIT)    // 4096
#define NKT (KSPLIT / BK)            // 128
#define ASTR 40
#define BSTR 40
#define ASTAGE (BM * ASTR)
#define BSTAGE (BN * BSTR)
#define SMEM_G1 ((2 * ASTAGE + 4 * BSTAGE) * 2)   // 102400 B

__global__ __launch_bounds__(256, 1) void k_gemm1(const float* __restrict__ adj) {
    extern __shared__ __align__(16) char smraw[];
    __half* Ah = reinterpret_cast<__half*>(smraw);
    __half* Bs = reinterpret_cast<__half*>(smraw + 2 * ASTAGE * 2);

    int tid = threadIdx.x;
    int m0 = blockIdx.x * BM;
    int kb = blockIdx.z * KSPLIT;
    const float*  Ag = adj + (size_t)m0 * N_NODES + kb;
    const __half* Bg = g_STh + kb;

    uint32_t sAh = (uint32_t)__cvta_generic_to_shared(Ah);
    uint32_t sB  = (uint32_t)__cvta_generic_to_shared(Bs);

    int ar = tid >> 1, ac = (tid & 1) * 16;

    float4 pa[4];
    auto ldgA = [&](int kt) {
        const float4* p = reinterpret_cast<const float4*>(
            Ag + (size_t)ar * N_NODES + kt * BK + ac);
#pragma unroll
        for (int i = 0; i < 4; i++) pa[i] = p[i];
    };
    auto stsA = [&](int st) {
        uint32_t d[8];
#pragma unroll
        for (int i = 0; i < 4; i++) {
            d[2 * i]     = packh2_scaled(pa[i].x, pa[i].y);
            d[2 * i + 1] = packh2_scaled(pa[i].z, pa[i].w);
        }
        uint4* dst = reinterpret_cast<uint4*>(Ah + st * ASTAGE + ar * ASTR + ac);
        dst[0] = make_uint4(d[0], d[1], d[2], d[3]);
        dst[1] = make_uint4(d[4], d[5], d[6], d[7]);
    };

    auto loadB = [&](int kt) {
        int st = kt & 3;
        int k0 = kt * BK;
#pragma unroll
        for (int i = 0; i < 4; i++) {
            int v = tid + i * 256;
            int r = v >> 2, c = v & 3;
            cp16(sB + (uint32_t)(st * BSTAGE + r * BSTR + c * 8) * 2,
                 Bg + (size_t)r * N_NODES + k0 + c * 8);
        }
        asm volatile("cp.async.commit_group;\n");
    };

    float acc[4][8][4];
#pragma unroll
    for (int a = 0; a < 4; a++)
#pragma unroll
        for (int b = 0; b < 8; b++)
#pragma unroll
            for (int c = 0; c < 4; c++) acc[a][b][c] = 0.f;

    int wid = tid >> 5, lane = tid & 31;
    int wm = (wid & 1) * 64;
    int wn = (wid >> 1) * 64;

    uint32_t Af[2][16], Bf[2][16];

    int a_row = lane & 15, a_half = (lane >> 4) * 8;
    int b_q = lane >> 3, b_r = lane & 7;
    int b_nfo = (b_q >> 1), b_half = (b_q & 1) * 8;

    auto fragload = [&](int buf, int ast, int bst, int k0) {
#pragma unroll
        for (int mf = 0; mf < 4; mf++) {
            uint32_t ad = sAh + (uint32_t)(ast * ASTAGE +
                (wm + mf * 16 + a_row) * ASTR + k0 + a_half) * 2;
            LDSM_X4(Af[buf][mf * 4 + 0], Af[buf][mf * 4 + 1],
                    Af[buf][mf * 4 + 2], Af[buf][mf * 4 + 3], ad);
        }
#pragma unroll
        for (int p = 0; p < 4; p++) {
            int nf = p * 2 + b_nfo;
            uint32_t ad = sB + (uint32_t)(bst * BSTAGE +
                (wn + nf * 8 + b_r) * BSTR + k0 + b_half) * 2;
            LDSM_X4(Bf[buf][p * 4 + 0], Bf[buf][p * 4 + 1],
                    Bf[buf][p * 4 + 2], Bf[buf][p * 4 + 3], ad);
        }
    };

    auto mma_all = [&](int buf) {
#pragma unroll
        for (int nf = 0; nf < 8; nf++) {
            uint32_t b0 = Bf[buf][(nf >> 1) * 4 + (nf & 1) * 2];
            uint32_t b1 = Bf[buf][(nf >> 1) * 4 + (nf & 1) * 2 + 1];
#pragma unroll
            for (int mf = 0; mf < 4; mf++) {
                asm volatile(
                    "mma.sync.aligned.m16n8k16.row.col.f32.f16.f16.f32 "
                    "{%0,%1,%2,%3}, {%4,%5,%6,%7}, {%8,%9}, {%0,%1,%2,%3};\n"
                    : "+f"(acc[mf][nf][0]), "+f"(acc[mf][nf][1]),
                      "+f"(acc[mf][nf][2]), "+f"(acc[mf][nf][3])
                    : "r"(Af[buf][mf * 4 + 0]), "r"(Af[buf][mf * 4 + 1]),
                      "r"(Af[buf][mf * 4 + 2]), "r"(Af[buf][mf * 4 + 3]),
                      "r"(b0), "r"(b1));
            }
        }
    };

    ldgA(0);
    loadB(0); loadB(1); loadB(2);
    stsA(0);
    ldgA(1);
    asm volatile("cp.async.wait_group 2;\n");
    __syncthreads();

    for (int kt = 0; kt < NKT; kt++) {
        if (kt + 3 < NKT) loadB(kt + 3);
        fragload(0, kt & 1, kt & 3, 0);
        fragload(1, kt & 1, kt & 3, 16);
        mma_all(0);
        if (kt + 1 < NKT) {
            stsA((kt + 1) & 1);
            if (kt + 2 < NKT) ldgA(kt + 2);
        }
        mma_all(1);
        if (kt + 1 < NKT) {
            int rem = NKT - 2 - kt;
            if (rem >= 2)      asm volatile("cp.async.wait_group 2;\n");
            else if (rem == 1) asm volatile("cp.async.wait_group 1;\n");
            else               asm volatile("cp.async.wait_group 0;\n");
            __syncthreads();
        }
    }

    int g = lane >> 2, tg = lane & 3;
    __half* P = g_Ph + (size_t)blockIdx.z * (N_NODES * 256);
#pragma unroll
    for (int mf = 0; mf < 4; mf++)
#pragma unroll
        for (int nf = 0; nf < 8; nf++) {
            int row = m0 + wm + mf * 16 + g;
            int col = wn + nf * 8 + 2 * tg;
            *reinterpret_cast<uint32_t*>(&P[(size_t)row * 256 + col]) =
                packh2(acc[mf][nf][0], acc[mf][nf][1]);
            *reinterpret_cast<uint32_t*>(&P[(size_t)(row + 8) * 256 + col]) =
                packh2(acc[mf][nf][2], acc[mf][nf][3]);
        }
}

// ---------------- K2b: combine (8 elems/thread) + fused losses block ----------------
__global__ void k_combine2(const float* __restrict__ thi,
                           const int* __restrict__ labels,
                           const int* __restrict__ tidx,
                           float* __restrict__ out)
{
    if (blockIdx.x == 512) {
        __shared__ float red[256];
        int tid = threadIdx.x;

        if (tid == 0) {
            float st[C_CLS];
            for (int c = 0; c < C_CLS; c++) st[c] = thi[c];
            for (int i = 1; i < C_CLS; i++) {
                float key = st[i]; int k = i - 1;
                while (k >= 0 && st[k] > key) { st[k + 1] = st[k]; k--; }
                st[k + 1] = key;
            }
            float sum = 0.f, mx = 0.f;
            for (int c = 0; c < C_CLS - 1; c++) {
                float d = fabsf(st[c + 1] - st[c]);
                sum += d; if (d > mx) mx = d;
            }
            float difference = sum / (mx + 1e-6f);
            out[(size_t)2 * ND] = 0.1f / (1e-6f + difference);
        }

        float accn = 0.f;
        for (int t = tid; t < T_TRAIN; t += 256) {
            int row = tidx[t];
            int lab = labels[row];
            float l[C_CLS]; float m = -1e30f;
#pragma unroll
            for (int c = 0; c < C_CLS; c++) { l[c] = g_pn[row * C_CLS + c]; m = fmaxf(m, l[c]); }
            float s = 0.f;
#pragma unroll
            for (int c = 0; c < C_CLS; c++) s += expf(l[c] - m);
            float lse = m + logf(s);
            float lp = 0.f;
#pragma unroll
            for (int c = 0; c < C_CLS; c++) if (c == lab) lp = l[c] - lse;
            accn += -lp;
        }
        red[tid] = accn;
        __syncthreads();
        for (int off = 128; off; off >>= 1) {
            if (tid < off) red[tid] += red[tid + off];
            __syncthreads();
        }
        if (tid == 0) out[(size_t)2 * ND + 1] = red[0] / (float)T_TRAIN * 0.1f;
        return;
    }

    int t = blockIdx.x * 256 + threadIdx.x;
    int n = t >> 4, d0 = (t & 15) * 8;
    size_t b = (size_t)n * 256;
    const size_t PS = (size_t)N_NODES * 256;
    uint4 r0 = *reinterpret_cast<const uint4*>(&g_Ph[b + d0]);
    uint4 r1 = *reinterpret_cast<const uint4*>(&g_Ph[PS + b + d0]);
    uint4 i0 = *reinterpret_cast<const uint4*>(&g_Ph[b + 128 + d0]);
    uint4 i1 = *reinterpret_cast<const uint4*>(&g_Ph[PS + b + 128 + d0]);
    float inr = g_in[n], ini = g_in[N_NODES + n];
    uint4 vr, vi;
#pragma unroll
    for (int q = 0; q < 4; q++) {
        float2 a0 = __half22float2(*reinterpret_cast<__half2*>(&(&r0.x)[q]));
        float2 a1 = __half22float2(*reinterpret_cast<__half2*>(&(&r1.x)[q]));
        float2 c0 = __half22float2(*reinterpret_cast<__half2*>(&(&i0.x)[q]));
        float2 c1 = __half22float2(*reinterpret_cast<__half2*>(&(&i1.x)[q]));
        float mrx = (a0.x + a1.x) * INV_SCALE, mry = (a0.y + a1.y) * INV_SCALE;
        float mix = (c0.x + c1.x) * INV_SCALE, miy = (c0.y + c1.y) * INV_SCALE;
        (&vr.x)[q] = packh2(inr * mrx - ini * mix, inr * mry - ini * miy);
        (&vi.x)[q] = packh2(inr * mix + ini * mrx, inr * miy + ini * mry);
    }
    *reinterpret_cast<uint4*>(&g_Msgh[b + d0])       = vr;
    *reinterpret_cast<uint4*>(&g_Msgh[b + 128 + d0]) = vi;
}

// ---------------- K3: MLP GEMM — single-stage full-K resident, fp16 m16n8k16 ----------------
#define MSTR2 264   // halfs per smem row (528B, 16B-mult; 132 words % 32 = 4 -> LDSM conflict-free)
#define SMEM_MLP (2 * 128 * MSTR2 * 2)   // 135168 B

__global__ __launch_bounds__(256, 1) void k_gemm_mlp(
    const float* __restrict__ br, const float* __restrict__ bi,
    const float* __restrict__ xr, const float* __restrict__ xi,
    float* __restrict__ out)
{
    extern __shared__ __align__(16) char smem_mlp[];
    __half* As2 = reinterpret_cast<__half*>(smem_mlp);
    __half* Bs2 = reinterpret_cast<__half*>(smem_mlp + 128 * MSTR2 * 2);

    int tid = threadIdx.x;
    int m0 = blockIdx.x * 128;
    int n0 = blockIdx.y * 128;
    const __half* Ag = g_Msgh + (size_t)m0 * 256;
    const __half* Bg = g_Wbigh + (size_t)n0 * 256;

    uint32_t sA = (uint32_t)__cvta_generic_to_shared(As2);
    uint32_t sB = (uint32_t)__cvta_generic_to_shared(Bs2);

    // single volley: 128 rows x 32 vec16 per operand = 4096 vec16; 16/thread
#pragma unroll
    for (int i = 0; i < 16; i++) {
        int v = tid + i * 256;
        int r = v >> 5, c = v & 31;
        cp16(sA + (uint32_t)(r * MSTR2 + c * 8) * 2, Ag + (size_t)r * 256 + c * 8);
        cp16(sB + (uint32_t)(r * MSTR2 + c * 8) * 2, Bg + (size_t)r * 256 + c * 8);
    }
    asm volatile("cp.async.commit_group;\n");
    asm volatile("cp.async.wait_group 0;\n");
    __syncthreads();

    float acc[2][8][4];
#pragma unroll
    for (int a = 0; a < 2; a++)
#pragma unroll
        for (int b = 0; b < 8; b++)
#pragma unroll
            for (int c = 0; c < 4; c++) acc[a][b][c] = 0.f;

    int wid = tid >> 5, lane = tid & 31;
    int wm = (wid & 3) * 32;   // warp tile 32x64
    int wn = (wid >> 2) * 64;

    int a_row = lane & 15, a_half = (lane >> 4) * 8;
    int b_q = lane >> 3, b_r = lane & 7;
    int b_nfo = (b_q >> 1), b_half = (b_q & 1) * 8;

    // 16 kk-rounds, no barriers — ILP across rounds hides LDS latency
#pragma unroll
    for (int kk = 0; kk < 16; kk++) {
        int k0 = kk * 16;
        uint32_t a[2][4], bf[16];
#pragma unroll
        for (int mf = 0; mf < 2; mf++) {
            uint32_t ad = sA + (uint32_t)((wm + mf * 16 + a_row) * MSTR2 + k0 + a_half) * 2;
            LDSM_X4(a[mf][0], a[mf][1], a[mf][2], a[mf][3], ad);
        }
#pragma unroll
        for (int p = 0; p < 4; p++) {
            int nf = p * 2 + b_nfo;
            uint32_t ad = sB + (uint32_t)((wn + nf * 8 + b_r) * MSTR2 + k0 + b_half) * 2;
            LDSM_X4(bf[p * 4 + 0], bf[p * 4 + 1], bf[p * 4 + 2], bf[p * 4 + 3], ad);
        }
#pragma unroll
        for (int nf = 0; nf < 8; nf++) {
            uint32_t b0 = bf[(nf >> 1) * 4 + (nf & 1) * 2];
            uint32_t b1 = bf[(nf >> 1) * 4 + (nf & 1) * 2 + 1];
#pragma unroll
            for (int mf = 0; mf < 2; mf++) {
                asm volatile(
                    "mma.sync.aligned.m16n8k16.row.col.f32.f16.f16.f32 "
                    "{%0,%1,%2,%3}, {%4,%5,%6,%7}, {%8,%9}, {%0,%1,%2,%3};\n"
                    : "+f"(acc[mf][nf][0]), "+f"(acc[mf][nf][1]),
                      "+f"(acc[mf][nf][2]), "+f"(acc[mf][nf][3])
                    : "r"(a[mf][0]), "r"(a[mf][1]), "r"(a[mf][2]), "r"(a[mf][3]),
                      "r"(b0), "r"(b1));
            }
        }
    }

    // fused epilogue: bias + residual + split, float2 vectorized
    int g = lane >> 2, tg = lane & 3;
#pragma unroll
    for (int mf = 0; mf < 2; mf++)
#pragma unroll
        for (int nf = 0; nf < 8; nf++) {
            int row = m0 + wm + mf * 16 + g;
            int col = n0 + wn + nf * 8 + 2 * tg;
            bool isreal = (col < 128);
            int c = isreal ? col : col - 128;
            const float* xb = isreal ? xr : xi;
            float bsign = isreal ? -1.f : 1.f;
            float bias0 = br[c]     + bsign * bi[c];
            float bias1 = br[c + 1] + bsign * bi[c + 1];
            size_t obase = isreal ? 0 : (size_t)ND;
#pragma unroll
            for (int h = 0; h < 2; h++) {
                int r = row + h * 8;
                float2 xv = *reinterpret_cast<const float2*>(&xb[(size_t)r * 128 + c]);
                float2 o;
                o.x = acc[mf][nf][h * 2]     + bias0 + xv.x;
                o.y = acc[mf][nf][h * 2 + 1] + bias1 + xv.y;
                *reinterpret_cast<float2*>(&out[obase + (size_t)r * 128 + c]) = o;
            }
        }
}

// ---------------- launch ----------------
extern "C" void kernel_launch(void* const* d_in, const int* in_sizes, int n_in,
                              void* d_out, int out_size)
{
    const float* x_real     = (const float*)d_in[0];
    const float* x_imag     = (const float*)d_in[1];
    const float* adj        = (const float*)d_in[2];
    const float* theta_real = (const float*)d_in[3];
    const float* theta_imag = (const float*)d_in[4];
    const float* W_r        = (const float*)d_in[5];
    const float* b_r        = (const float*)d_in[6];
    const float* W_i        = (const float*)d_in[7];
    const float* b_i        = (const float*)d_in[8];
    const float* Wc_r       = (const float*)d_in[9];
    const float* bc_r       = (const float*)d_in[10];
    const float* Wc_i       = (const float*)d_in[11];
    const float* bc_i       = (const float*)d_in[12];
    const int*   labels     = (const int*)d_in[13];
    const int*   train_idx  = (const int*)d_in[14];
    float* out = (float*)d_out;

    cudaFuncSetAttribute(k_gemm1, cudaFuncAttributeMaxDynamicSharedMemorySize, SMEM_G1);
    cudaFuncSetAttribute(k_gemm_mlp, cudaFuncAttributeMaxDynamicSharedMemorySize, SMEM_MLP);

    k_node_prep<<<320, 1024>>>(x_real, x_imag, Wc_r, Wc_i, bc_r, bc_i,
                               theta_real, theta_imag, W_r, W_i);
    k_gemm1<<<dim3(64, 1, NSPLIT), 256, SMEM_G1>>>(adj);
    k_combine2<<<513, 256>>>(theta_imag, labels, train_idx, out);
    k_gemm_mlp<<<dim3(64, 2), 256, SMEM_MLP>>>(b_r, b_i, x_real, x_imag, out);
}

// round 17
// speedup vs baseline: 1.4194x; 1.0301x over previous
#include <cuda_runtime.h>
#include <cuda_fp16.h>
#include <cstdint>

#define N_NODES 8192
#define D_FEAT  128
#define C_CLS   10
#define T_TRAIN 1024
#define ND (N_NODES * D_FEAT)

#define INV_SCALE (1.0f / 4096.0f)

// ---------------- scratch (device globals; no allocation allowed) ----------------
__device__ __align__(128) __half g_STh[256 * N_NODES];   // S^T fp16 [256,8192] K-major (GEMM B)
__device__ __align__(128) __half g_Ph[2 * N_NODES * 256];// K-split partial sums (fp16)
__device__ __align__(128) float  g_in[2 * N_NODES];      // in_r, in_i
__device__ __align__(128) float  g_pn[N_NODES * C_CLS];  // pseudo_norm
__device__ __align__(128) __half g_Wbigh[256 * 256];     // [[Wr,-Wi],[Wi,Wr]] K-major fp16

// ---------------- helpers ----------------
__device__ __forceinline__ void cp16(uint32_t smem, const void* g) {
    asm volatile("cp.async.cg.shared.global [%0], [%1], 16;\n" :: "r"(smem), "l"(g));
}
// exact x4096 via exponent add (adj >= 0; 0 stays ~0 after f16 round)
__device__ __forceinline__ uint32_t packh2_scaled(float x, float y) {
    float xs = __uint_as_float(__float_as_uint(x) + 0x06000000u);
    float ys = __uint_as_float(__float_as_uint(y) + 0x06000000u);
    __half2 h = __floats2half2_rn(xs, ys);
    return *reinterpret_cast<uint32_t*>(&h);
}
__device__ __forceinline__ uint32_t packh2(float x, float y) {
    __half2 h = __floats2half2_rn(x, y);
    return *reinterpret_cast<uint32_t*>(&h);
}
#define LDSM_X4(r0, r1, r2, r3, addr) \
    asm volatile("ldmatrix.sync.aligned.m8n8.x4.shared.b16 {%0,%1,%2,%3}, [%4];" \
        : "=r"(r0), "=r"(r1), "=r"(r2), "=r"(r3) : "r"(addr))

// ---------------- K1: per-node prep + fused transpose (+ fp16 Wbig build blocks) ----------------
#define TSTR 34   // halfs per sT row (68B, conflict-free)

__global__ __launch_bounds__(1024) void k_node_prep(
    const float* __restrict__ xr_g, const float* __restrict__ xi_g,
    const float* __restrict__ Wcr, const float* __restrict__ Wci,
    const float* __restrict__ bcr, const float* __restrict__ bci,
    const float* __restrict__ thr, const float* __restrict__ thi,
    const float* __restrict__ Wr_mlp, const float* __restrict__ Wi_mlp)
{
    if (blockIdx.x >= 256) {
        int idx = (blockIdx.x - 256) * 1024 + threadIdx.x;   // 64 blocks x 1024 = 65536
        int d = idx >> 8, e = idx & 255;
        float v;
        if (d < 128) v = (e < 128) ? Wr_mlp[d * 128 + e] : -Wi_mlp[d * 128 + (e - 128)];
        else {
            int dd = d - 128;
            v = (e < 128) ? Wi_mlp[dd * 128 + e] : Wr_mlp[dd * 128 + (e - 128)];
        }
        g_Wbigh[idx] = __float2half(v);
        return;
    }

    __shared__ float sWr[C_CLS * 128], sWi[C_CLS * 128];
    __shared__ float sb[4 * C_CLS];
    __shared__ __half sT[256 * TSTR];
    int tid = threadIdx.x;
    for (int i = tid; i < C_CLS * 128; i += 1024) { sWr[i] = Wcr[i]; sWi[i] = Wci[i]; }
    if (tid < C_CLS) {
        sb[tid] = bcr[tid]; sb[C_CLS + tid] = bci[tid];
        sb[2 * C_CLS + tid] = thr[tid]; sb[3 * C_CLS + tid] = thi[tid];
    }
    __syncthreads();

    int wid = tid >> 5, lane = tid & 31;
    int j = blockIdx.x * 32 + wid;

    float xr[4], xi[4];
#pragma unroll
    for (int k = 0; k < 4; k++) {
        xr[k] = xr_g[j * 128 + lane + 32 * k];
        xi[k] = xi_g[j * 128 + lane + 32 * k];
    }

    float pn[C_CLS];
#pragma unroll
    for (int c = 0; c < C_CLS; c++) {
        float p1 = 0.f, p2 = 0.f, p3 = 0.f, p4 = 0.f;
#pragma unroll
        for (int k = 0; k < 4; k++) {
            float wr = sWr[c * 128 + lane + 32 * k];
            float wi = sWi[c * 128 + lane + 32 * k];
            p1 += xr[k] * wr; p2 += xi[k] * wr;
            p3 += xi[k] * wi; p4 += xr[k] * wi;
        }
#pragma unroll
        for (int off = 16; off; off >>= 1) {
            p1 += __shfl_xor_sync(0xffffffffu, p1, off);
            p2 += __shfl_xor_sync(0xffffffffu, p2, off);
            p3 += __shfl_xor_sync(0xffffffffu, p3, off);
            p4 += __shfl_xor_sync(0xffffffffu, p4, off);
        }
        float cr = p1 + sb[c] - p3 - sb[C_CLS + c];
        float ci = p2 + sb[c] + p4 + sb[C_CLS + c];
        pn[c] = sqrtf(cr * cr + ci * ci);
    }

    float m = pn[0];
#pragma unroll
    for (int c = 1; c < C_CLS; c++) m = fmaxf(m, pn[c]);
    float s = 0.f, e[C_CLS];
#pragma unroll
    for (int c = 0; c < C_CLS; c++) { e[c] = expf(pn[c] - m); s += e[c]; }
    float inv = 1.0f / s, inr = 0.f, ini = 0.f;
#pragma unroll
    for (int c = 0; c < C_CLS; c++) {
        float sc = e[c] * inv;
        inr += sc * sb[2 * C_CLS + c];
        ini += sc * sb[3 * C_CLS + c];
    }

    if (lane == 0) {
#pragma unroll
        for (int c = 0; c < C_CLS; c++) g_pn[j * C_CLS + c] = pn[c];
        g_in[j] = inr; g_in[N_NODES + j] = ini;
    }

#pragma unroll
    for (int k = 0; k < 4; k++) {
        int d = lane + 32 * k;
        sT[d * TSTR + wid]         = __float2half(inr * xr[k] + ini * xi[k]);
        sT[(128 + d) * TSTR + wid] = __float2half(inr * xi[k] - ini * xr[k]);
    }
    __syncthreads();

    {
        int r = tid >> 2, q = tid & 3;
        const __half* src = &sT[r * TSTR + q * 8];
        uint32_t w0 = *reinterpret_cast<const uint32_t*>(src);
        uint32_t w1 = *reinterpret_cast<const uint32_t*>(src + 2);
        uint32_t w2 = *reinterpret_cast<const uint32_t*>(src + 4);
        uint32_t w3 = *reinterpret_cast<const uint32_t*>(src + 6);
        *reinterpret_cast<uint4*>(&g_STh[(size_t)r * N_NODES + blockIdx.x * 32 + q * 8]) =
            make_uint4(w0, w1, w2, w3);
    }
}

// ================= GEMM1 (frozen round-10 mainloop): fp16 mma + ldmatrix + frag DB =================
#define BM 128
#define BN 256
#define BK 32
#define NSPLIT 2
#define KSPLIT (N_NODES / NSPLIT)    // 4096
#define NKT (KSPLIT / BK)            // 128
#define ASTR 40
#define BSTR 40
#define ASTAGE (BM * ASTR)
#define BSTAGE (BN * BSTR)
#define SMEM_G1 ((2 * ASTAGE + 4 * BSTAGE) * 2)   // 102400 B

__global__ __launch_bounds__(256, 1) void k_gemm1(const float* __restrict__ adj) {
    extern __shared__ __align__(16) char smraw[];
    __half* Ah = reinterpret_cast<__half*>(smraw);
    __half* Bs = reinterpret_cast<__half*>(smraw + 2 * ASTAGE * 2);

    int tid = threadIdx.x;
    int m0 = blockIdx.x * BM;
    int kb = blockIdx.z * KSPLIT;
    const float*  Ag = adj + (size_t)m0 * N_NODES + kb;
    const __half* Bg = g_STh + kb;

    uint32_t sAh = (uint32_t)__cvta_generic_to_shared(Ah);
    uint32_t sB  = (uint32_t)__cvta_generic_to_shared(Bs);

    int ar = tid >> 1, ac = (tid & 1) * 16;

    float4 pa[4];
    auto ldgA = [&](int kt) {
        const float4* p = reinterpret_cast<const float4*>(
            Ag + (size_t)ar * N_NODES + kt * BK + ac);
#pragma unroll
        for (int i = 0; i < 4; i++) pa[i] = p[i];
    };
    auto stsA = [&](int st) {
        uint32_t d[8];
#pragma unroll
        for (int i = 0; i < 4; i++) {
            d[2 * i]     = packh2_scaled(pa[i].x, pa[i].y);
            d[2 * i + 1] = packh2_scaled(pa[i].z, pa[i].w);
        }
        uint4* dst = reinterpret_cast<uint4*>(Ah + st * ASTAGE + ar * ASTR + ac);
        dst[0] = make_uint4(d[0], d[1], d[2], d[3]);
        dst[1] = make_uint4(d[4], d[5], d[6], d[7]);
    };

    auto loadB = [&](int kt) {
        int st = kt & 3;
        int k0 = kt * BK;
#pragma unroll
        for (int i = 0; i < 4; i++) {
            int v = tid + i * 256;
            int r = v >> 2, c = v & 3;
            cp16(sB + (uint32_t)(st * BSTAGE + r * BSTR + c * 8) * 2,
                 Bg + (size_t)r * N_NODES + k0 + c * 8);
        }
        asm volatile("cp.async.commit_group;\n");
    };

    float acc[4][8][4];
#pragma unroll
    for (int a = 0; a < 4; a++)
#pragma unroll
        for (int b = 0; b < 8; b++)
#pragma unroll
            for (int c = 0; c < 4; c++) acc[a][b][c] = 0.f;

    int wid = tid >> 5, lane = tid & 31;
    int wm = (wid & 1) * 64;
    int wn = (wid >> 1) * 64;

    uint32_t Af[2][16], Bf[2][16];

    int a_row = lane & 15, a_half = (lane >> 4) * 8;
    int b_q = lane >> 3, b_r = lane & 7;
    int b_nfo = (b_q >> 1), b_half = (b_q & 1) * 8;

    auto fragload = [&](int buf, int ast, int bst, int k0) {
#pragma unroll
        for (int mf = 0; mf < 4; mf++) {
            uint32_t ad = sAh + (uint32_t)(ast * ASTAGE +
                (wm + mf * 16 + a_row) * ASTR + k0 + a_half) * 2;
            LDSM_X4(Af[buf][mf * 4 + 0], Af[buf][mf * 4 + 1],
                    Af[buf][mf * 4 + 2], Af[buf][mf * 4 + 3], ad);
        }
#pragma unroll
        for (int p = 0; p < 4; p++) {
            int nf = p * 2 + b_nfo;
            uint32_t ad = sB + (uint32_t)(bst * BSTAGE +
                (wn + nf * 8 + b_r) * BSTR + k0 + b_half) * 2;
            LDSM_X4(Bf[buf][p * 4 + 0], Bf[buf][p * 4 + 1],
                    Bf[buf][p * 4 + 2], Bf[buf][p * 4 + 3], ad);
        }
    };

    auto mma_all = [&](int buf) {
#pragma unroll
        for (int nf = 0; nf < 8; nf++) {
            uint32_t b0 = Bf[buf][(nf >> 1) * 4 + (nf & 1) * 2];
            uint32_t b1 = Bf[buf][(nf >> 1) * 4 + (nf & 1) * 2 + 1];
#pragma unroll
            for (int mf = 0; mf < 4; mf++) {
                asm volatile(
                    "mma.sync.aligned.m16n8k16.row.col.f32.f16.f16.f32 "
                    "{%0,%1,%2,%3}, {%4,%5,%6,%7}, {%8,%9}, {%0,%1,%2,%3};\n"
                    : "+f"(acc[mf][nf][0]), "+f"(acc[mf][nf][1]),
                      "+f"(acc[mf][nf][2]), "+f"(acc[mf][nf][3])
                    : "r"(Af[buf][mf * 4 + 0]), "r"(Af[buf][mf * 4 + 1]),
                      "r"(Af[buf][mf * 4 + 2]), "r"(Af[buf][mf * 4 + 3]),
                      "r"(b0), "r"(b1));
            }
        }
    };

    ldgA(0);
    loadB(0); loadB(1); loadB(2);
    stsA(0);
    ldgA(1);
    asm volatile("cp.async.wait_group 2;\n");
    __syncthreads();

    for (int kt = 0; kt < NKT; kt++) {
        if (kt + 3 < NKT) loadB(kt + 3);
        fragload(0, kt & 1, kt & 3, 0);
        fragload(1, kt & 1, kt & 3, 16);
        mma_all(0);
        if (kt + 1 < NKT) {
            stsA((kt + 1) & 1);
            if (kt + 2 < NKT) ldgA(kt + 2);
        }
        mma_all(1);
        if (kt + 1 < NKT) {
            int rem = NKT - 2 - kt;
            if (rem >= 2)      asm volatile("cp.async.wait_group 2;\n");
            else if (rem == 1) asm volatile("cp.async.wait_group 1;\n");
            else               asm volatile("cp.async.wait_group 0;\n");
            __syncthreads();
        }
    }

    int g = lane >> 2, tg = lane & 3;
    __half* P = g_Ph + (size_t)blockIdx.z * (N_NODES * 256);
#pragma unroll
    for (int mf = 0; mf < 4; mf++)
#pragma unroll
        for (int nf = 0; nf < 8; nf++) {
            int row = m0 + wm + mf * 16 + g;
            int col = wn + nf * 8 + 2 * tg;
            *reinterpret_cast<uint32_t*>(&P[(size_t)row * 256 + col]) =
                packh2(acc[mf][nf][0], acc[mf][nf][1]);
            *reinterpret_cast<uint32_t*>(&P[(size_t)(row + 8) * 256 + col]) =
                packh2(acc[mf][nf][2], acc[mf][nf][3]);
        }
}

// ---------------- K3: MLP GEMM with fused combine A-path (+ losses block) ----------------
#define MSTR2 264   // halfs per smem row (528B, 16B-mult; LDSM conflict-free)
#define SMEM_MLP (2 * 128 * MSTR2 * 2)   // 135168 B

__global__ __launch_bounds__(256, 1) void k_gemm_mlp(
    const float* __restrict__ br, const float* __restrict__ bi,
    const float* __restrict__ xr, const float* __restrict__ xi,
    const float* __restrict__ thi, const int* __restrict__ labels,
    const int* __restrict__ tidx,
    float* __restrict__ out)
{
    if (blockIdx.x == 64) {
        if (blockIdx.y != 0) return;
        // ---- losses (one block) ----
        __shared__ float red[256];
        int tid = threadIdx.x;
        if (tid == 0) {
            float st[C_CLS];
            for (int c = 0; c < C_CLS; c++) st[c] = thi[c];
            for (int i = 1; i < C_CLS; i++) {
                float key = st[i]; int k = i - 1;
                while (k >= 0 && st[k] > key) { st[k + 1] = st[k]; k--; }
                st[k + 1] = key;
            }
            float sum = 0.f, mx = 0.f;
            for (int c = 0; c < C_CLS - 1; c++) {
                float d = fabsf(st[c + 1] - st[c]);
                sum += d; if (d > mx) mx = d;
            }
            float difference = sum / (mx + 1e-6f);
            out[(size_t)2 * ND] = 0.1f / (1e-6f + difference);
        }
        float accn = 0.f;
        for (int t = tid; t < T_TRAIN; t += 256) {
            int row = tidx[t];
            int lab = labels[row];
            float l[C_CLS]; float m = -1e30f;
#pragma unroll
            for (int c = 0; c < C_CLS; c++) { l[c] = g_pn[row * C_CLS + c]; m = fmaxf(m, l[c]); }
            float s = 0.f;
#pragma unroll
            for (int c = 0; c < C_CLS; c++) s += expf(l[c] - m);
            float lse = m + logf(s);
            float lp = 0.f;
#pragma unroll
            for (int c = 0; c < C_CLS; c++) if (c == lab) lp = l[c] - lse;
            accn += -lp;
        }
        red[tid] = accn;
        __syncthreads();
        for (int off = 128; off; off >>= 1) {
            if (tid < off) red[tid] += red[tid + off];
            __syncthreads();
        }
        if (tid == 0) out[(size_t)2 * ND + 1] = red[0] / (float)T_TRAIN * 0.1f;
        return;
    }

    extern __shared__ __align__(16) char smem_mlp[];
    __half* As2 = reinterpret_cast<__half*>(smem_mlp);
    __half* Bs2 = reinterpret_cast<__half*>(smem_mlp + 128 * MSTR2 * 2);

    int tid = threadIdx.x;
    int m0 = blockIdx.x * 128;
    int n0 = blockIdx.y * 128;
    const __half* Bg = g_Wbigh + (size_t)n0 * 256;

    uint32_t sA = (uint32_t)__cvta_generic_to_shared(As2);
    uint32_t sB = (uint32_t)__cvta_generic_to_shared(Bs2);

    // B volley (cp.async)
#pragma unroll
    for (int i = 0; i < 16; i++) {
        int v = tid + i * 256;
        int r = v >> 5, c = v & 31;
        cp16(sB + (uint32_t)(r * MSTR2 + c * 8) * 2, Bg + (size_t)r * 256 + c * 8);
    }
    asm volatile("cp.async.commit_group;\n");

    // A path: load g_Ph splits, combine diag(in)*(P0+P1)*INV_SCALE, store fp16 smem
    {
        int r = tid >> 1, seg = (tid & 1) * 64;   // row 0..127, 64 d-cols
        size_t b = (size_t)(m0 + r) * 256;
        const size_t PS = (size_t)N_NODES * 256;
        float inr = g_in[m0 + r], ini = g_in[N_NODES + m0 + r];
#pragma unroll
        for (int q8 = 0; q8 < 8; q8++) {
            int d0 = seg + q8 * 8;
            uint4 r0 = *reinterpret_cast<const uint4*>(&g_Ph[b + d0]);
            uint4 r1 = *reinterpret_cast<const uint4*>(&g_Ph[PS + b + d0]);
            uint4 i0 = *reinterpret_cast<const uint4*>(&g_Ph[b + 128 + d0]);
            uint4 i1 = *reinterpret_cast<const uint4*>(&g_Ph[PS + b + 128 + d0]);
            uint4 vr, vi;
#pragma unroll
            for (int q = 0; q < 4; q++) {
                float2 a0 = __half22float2(*reinterpret_cast<__half2*>(&(&r0.x)[q]));
                float2 a1 = __half22float2(*reinterpret_cast<__half2*>(&(&r1.x)[q]));
                float2 c0 = __half22float2(*reinterpret_cast<__half2*>(&(&i0.x)[q]));
                float2 c1 = __half22float2(*reinterpret_cast<__half2*>(&(&i1.x)[q]));
                float mrx = (a0.x + a1.x) * INV_SCALE, mry = (a0.y + a1.y) * INV_SCALE;
                float mix = (c0.x + c1.x) * INV_SCALE, miy = (c0.y + c1.y) * INV_SCALE;
                (&vr.x)[q] = packh2(inr * mrx - ini * mix, inr * mry - ini * miy);
                (&vi.x)[q] = packh2(inr * mix + ini * mrx, inr * miy + ini * mry);
            }
            *reinterpret_cast<uint4*>(&As2[r * MSTR2 + d0])       = vr;
            *reinterpret_cast<uint4*>(&As2[r * MSTR2 + 128 + d0]) = vi;
        }
    }

    asm volatile("cp.async.wait_group 0;\n");
    __syncthreads();

    float acc[2][8][4];
#pragma unroll
    for (int a = 0; a < 2; a++)
#pragma unroll
        for (int b = 0; b < 8; b++)
#pragma unroll
            for (int c = 0; c < 4; c++) acc[a][b][c] = 0.f;

    int wid = tid >> 5, lane = tid & 31;
    int wm = (wid & 3) * 32;   // warp tile 32x64
    int wn = (wid >> 2) * 64;

    int a_row = lane & 15, a_half = (lane >> 4) * 8;
    int b_q = lane >> 3, b_r = lane & 7;
    int b_nfo = (b_q >> 1), b_half = (b_q & 1) * 8;

#pragma unroll
    for (int kk = 0; kk < 16; kk++) {
        int k0 = kk * 16;
        uint32_t a[2][4], bf[16];
#pragma unroll
        for (int mf = 0; mf < 2; mf++) {
            uint32_t ad = sA + (uint32_t)((wm + mf * 16 + a_row) * MSTR2 + k0 + a_half) * 2;
            LDSM_X4(a[mf][0], a[mf][1], a[mf][2], a[mf][3], ad);
        }
#pragma unroll
        for (int p = 0; p < 4; p++) {
            int nf = p * 2 + b_nfo;
            uint32_t ad = sB + (uint32_t)((wn + nf * 8 + b_r) * MSTR2 + k0 + b_half) * 2;
            LDSM_X4(bf[p * 4 + 0], bf[p * 4 + 1], bf[p * 4 + 2], bf[p * 4 + 3], ad);
        }
#pragma unroll
        for (int nf = 0; nf < 8; nf++) {
            uint32_t b0 = bf[(nf >> 1) * 4 + (nf & 1) * 2];
            uint32_t b1 = bf[(nf >> 1) * 4 + (nf & 1) * 2 + 1];
#pragma unroll
            for (int mf = 0; mf < 2; mf++) {
                asm volatile(
                    "mma.sync.aligned.m16n8k16.row.col.f32.f16.f16.f32 "
                    "{%0,%1,%2,%3}, {%4,%5,%6,%7}, {%8,%9}, {%0,%1,%2,%3};\n"
                    : "+f"(acc[mf][nf][0]), "+f"(acc[mf][nf][1]),
                      "+f"(acc[mf][nf][2]), "+f"(acc[mf][nf][3])
                    : "r"(a[mf][0]), "r"(a[mf][1]), "r"(a[mf][2]), "r"(a[mf][3]),
                      "r"(b0), "r"(b1));
            }
        }
    }

    // fused epilogue: bias + residual + split, float2 vectorized
    int g = lane >> 2, tg = lane & 3;
#pragma unroll
    for (int mf = 0; mf < 2; mf++)
#pragma unroll
        for (int nf = 0; nf < 8; nf++) {
            int row = m0 + wm + mf * 16 + g;
            int col = n0 + wn + nf * 8 + 2 * tg;
            bool isreal = (col < 128);
            int c = isreal ? col : col - 128;
            const float* xb = isreal ? xr : xi;
            float bsign = isreal ? -1.f : 1.f;
            float bias0 = br[c]     + bsign * bi[c];
            float bias1 = br[c + 1] + bsign * bi[c + 1];
            size_t obase = isreal ? 0 : (size_t)ND;
#pragma unroll
            for (int h = 0; h < 2; h++) {
                int r = row + h * 8;
                float2 xv = *reinterpret_cast<const float2*>(&xb[(size_t)r * 128 + c]);
                float2 o;
                o.x = acc[mf][nf][h * 2]     + bias0 + xv.x;
                o.y = acc[mf][nf][h * 2 + 1] + bias1 + xv.y;
                *reinterpret_cast<float2*>(&out[obase + (size_t)r * 128 + c]) = o;
            }
        }
}

// ---------------- launch ----------------
extern "C" void kernel_launch(void* const* d_in, const int* in_sizes, int n_in,
                              void* d_out, int out_size)
{
    const float* x_real     = (const float*)d_in[0];
    const float* x_imag     = (const float*)d_in[1];
    const float* adj        = (const float*)d_in[2];
    const float* theta_real = (const float*)d_in[3];
    const float* theta_imag = (const float*)d_in[4];
    const float* W_r        = (const float*)d_in[5];
    const float* b_r        = (const float*)d_in[6];
    const float* W_i        = (const float*)d_in[7];
    const float* b_i        = (const float*)d_in[8];
    const float* Wc_r       = (const float*)d_in[9];
    const float* bc_r       = (const float*)d_in[10];
    const float* Wc_i       = (const float*)d_in[11];
    const float* bc_i       = (const float*)d_in[12];
    const int*   labels     = (const int*)d_in[13];
    const int*   train_idx  = (const int*)d_in[14];
    float* out = (float*)d_out;

    cudaFuncSetAttribute(k_gemm1, cudaFuncAttributeMaxDynamicSharedMemorySize, SMEM_G1);
    cudaFuncSetAttribute(k_gemm_mlp, cudaFuncAttributeMaxDynamicSharedMemorySize, SMEM_MLP);

    k_node_prep<<<320, 1024>>>(x_real, x_imag, Wc_r, Wc_i, bc_r, bc_i,
                               theta_real, theta_imag, W_r, W_i);
    k_gemm1<<<dim3(64, 1, NSPLIT), 256, SMEM_G1>>>(adj);
    k_gemm_mlp<<<dim3(65, 2), 256, SMEM_MLP>>>(b_r, b_i, x_real, x_imag,
                                               theta_imag, labels, train_idx, out);
}